// round 1
// baseline (speedup 1.0000x reference)
#include <cuda_runtime.h>

// Problem constants
#define B_     8
#define C_     512
#define NH_    8
#define HD_    64
#define NN_    1024        // H*W = 32*32
#define MQKV_  1536        // 3*C
#define SCALE_ 0.125f      // hd^-0.5

// Scratch (static device globals: allocation-free)
__device__ float g_qkv[B_ * MQKV_ * NN_];   // [b][h*192 + t*64 + d][n]  (t=0:q,1:k,2:v)
__device__ float g_ao [B_ * C_   * NN_];    // attention output [b][c][n]

// ---------------------------------------------------------------------------
// GEMM: out[b][m][n] = sum_c W[m][c] * X[b][c][n] (+ bias[m])
// Tile 128x128, K-chunk 8, 256 threads, 8x8 microtile.
// X layout: [b][512][1024] for both uses (x input and g_ao).
// ---------------------------------------------------------------------------
__global__ __launch_bounds__(256, 2)
void gemm_kernel(const float* __restrict__ W, const float* __restrict__ X,
                 const float* __restrict__ bias, float* __restrict__ out, int M)
{
    __shared__ float As[8][128];   // As[c][m]  (W transposed chunk)
    __shared__ float Bs[8][128];   // Bs[c][n]

    const int tid = threadIdx.x;
    const int tx = tid & 15, ty = tid >> 4;
    const int n0 = blockIdx.x * 128;
    const int m0 = blockIdx.y * 128;
    const int b  = blockIdx.z;
    const float* Xb = X + (size_t)b * C_ * NN_;

    // load index decomposition
    const int ar = tid >> 1, ac = (tid & 1) * 4;      // A: 128 rows x 8 cols
    const int br = tid >> 5, bc = (tid & 31) * 4;     // B: 8 rows x 128 cols

    float acc[8][8] = {};

    for (int c0 = 0; c0 < C_; c0 += 8) {
        float4 av = *(const float4*)&W [(m0 + ar) * C_  + c0 + ac];
        float4 bv = *(const float4*)&Xb[(c0 + br) * NN_ + n0 + bc];
        __syncthreads();   // all reads of previous tiles complete
        As[ac + 0][ar] = av.x;
        As[ac + 1][ar] = av.y;
        As[ac + 2][ar] = av.z;
        As[ac + 3][ar] = av.w;
        *(float4*)&Bs[br][bc] = bv;
        __syncthreads();

#pragma unroll
        for (int kk = 0; kk < 8; kk++) {
            float4 a0 = *(const float4*)&As[kk][ty * 8];
            float4 a1 = *(const float4*)&As[kk][ty * 8 + 4];
            float4 b0 = *(const float4*)&Bs[kk][tx * 8];
            float4 b1 = *(const float4*)&Bs[kk][tx * 8 + 4];
            float a[8] = {a0.x, a0.y, a0.z, a0.w, a1.x, a1.y, a1.z, a1.w};
            float bb[8] = {b0.x, b0.y, b0.z, b0.w, b1.x, b1.y, b1.z, b1.w};
#pragma unroll
            for (int i = 0; i < 8; i++)
#pragma unroll
                for (int j = 0; j < 8; j++)
                    acc[i][j] += a[i] * bb[j];
        }
    }

    float bval[8];
#pragma unroll
    for (int i = 0; i < 8; i++)
        bval[i] = bias ? bias[m0 + ty * 8 + i] : 0.0f;

    float* ob = out + (size_t)b * M * NN_;
#pragma unroll
    for (int i = 0; i < 8; i++) {
        int m = m0 + ty * 8 + i;
#pragma unroll
        for (int j = 0; j < 8; j++) acc[i][j] += bval[i];
        *(float4*)&ob[(size_t)m * NN_ + n0 + tx * 8]     =
            make_float4(acc[i][0], acc[i][1], acc[i][2], acc[i][3]);
        *(float4*)&ob[(size_t)m * NN_ + n0 + tx * 8 + 4] =
            make_float4(acc[i][4], acc[i][5], acc[i][6], acc[i][7]);
    }
}

// ---------------------------------------------------------------------------
// Fused attention (flash-style, softmax over the KEY axis n):
//   s[n][m] = scale * sum_d k[d][n] * q[d][m]
//   p = softmax_n(s);   out[d][m] = sum_n v[d][n] * p[n][m]
// One block per (b*nh, m-tile of 128 queries). n processed in chunks of 64.
// Dynamic smem layout (floats):
//   Qs [64][128], Ps [64][132], KV [64*68] (K then V-transposed),
//   red[2][128], rmax[128], rsum[128], alph[128]
// ---------------------------------------------------------------------------
#define ATTN_SMEM_FLOATS (64*128 + 64*132 + 64*68 + 256 + 128 + 128 + 128)
#define ATTN_SMEM_BYTES  (ATTN_SMEM_FLOATS * 4)

__global__ __launch_bounds__(256)
void attn_kernel(const float* __restrict__ qkv, float* __restrict__ ao)
{
    extern __shared__ float sm[];
    float* Qs   = sm;                 // [64][128]
    float* Ps   = Qs + 64 * 128;      // [64][132]
    float* KV   = Ps + 64 * 132;      // [64*68]
    float* red  = KV + 64 * 68;       // [2][128]
    float* rmax = red + 256;          // [128]
    float* rsum = rmax + 128;         // [128]
    float* alph = rsum + 128;         // [128]

    const int tid = threadIdx.x;
    const int tx = tid & 15, ty = tid >> 4;
    const int m0 = blockIdx.x * 128;
    const int bh = blockIdx.y;                       // b*8 + h
    const float* qp = qkv + (size_t)(bh * 192 +   0) * NN_;
    const float* kp = qkv + (size_t)(bh * 192 +  64) * NN_;
    const float* vp = qkv + (size_t)(bh * 192 + 128) * NN_;

    // Load Q tile [d=64][m=128]
    for (int i = tid; i < 64 * 32; i += 256) {
        int d = i >> 5, g = i & 31;
        *(float4*)&Qs[d * 128 + g * 4] =
            *(const float4*)&qp[(size_t)d * NN_ + m0 + g * 4];
    }
    if (tid < 128) { rmax[tid] = -1e30f; rsum[tid] = 0.0f; }

    float acc[4][8] = {};   // out accumulators: d = ty*4+i, m = tx*8+j
    const int col = tid & 127, half = tid >> 7;

    __syncthreads();

    for (int n0 = 0; n0 < NN_; n0 += 64) {
        // --- load K chunk into KV as Ks[d][n] (stride 68) ---
        for (int i = tid; i < 64 * 16; i += 256) {
            int d = i >> 4, g = i & 15;
            *(float4*)&KV[d * 68 + g * 4] =
                *(const float4*)&kp[(size_t)d * NN_ + n0 + g * 4];
        }
        __syncthreads();

        // --- S = K^T Q : s[n][m], thread n=ty*4.., m=tx*8.. ---
        float s[4][8] = {};
#pragma unroll 8
        for (int d = 0; d < 64; d++) {
            float4 kv4 = *(const float4*)&KV[d * 68 + ty * 4];
            float4 q0  = *(const float4*)&Qs[d * 128 + tx * 8];
            float4 q1  = *(const float4*)&Qs[d * 128 + tx * 8 + 4];
            float kn[4] = {kv4.x, kv4.y, kv4.z, kv4.w};
            float qm[8] = {q0.x, q0.y, q0.z, q0.w, q1.x, q1.y, q1.z, q1.w};
#pragma unroll
            for (int i = 0; i < 4; i++)
#pragma unroll
                for (int j = 0; j < 8; j++)
                    s[i][j] += kn[i] * qm[j];
        }
#pragma unroll
        for (int i = 0; i < 4; i++) {
            *(float4*)&Ps[(ty * 4 + i) * 132 + tx * 8] =
                make_float4(s[i][0]*SCALE_, s[i][1]*SCALE_, s[i][2]*SCALE_, s[i][3]*SCALE_);
            *(float4*)&Ps[(ty * 4 + i) * 132 + tx * 8 + 4] =
                make_float4(s[i][4]*SCALE_, s[i][5]*SCALE_, s[i][6]*SCALE_, s[i][7]*SCALE_);
        }
        __syncthreads();  // S visible; all KV(K) reads complete

        // --- softmax pass A: per-column chunk max; prefetch V from GMEM ---
        float4 vreg[4];
#pragma unroll
        for (int j = 0; j < 4; j++) {
            int idx = tid + j * 256;
            int d = idx >> 4, g = idx & 15;
            vreg[j] = *(const float4*)&vp[(size_t)d * NN_ + n0 + g * 4];
        }
        float lm = -1e30f;
#pragma unroll
        for (int n = half * 32; n < half * 32 + 32; n++)
            lm = fmaxf(lm, Ps[n * 132 + col]);
        red[half * 128 + col] = lm;
        __syncthreads();

        if (tid < 128) {
            float cm = fmaxf(red[col], red[128 + col]);
            float om = rmax[col];
            float nm = fmaxf(om, cm);
            alph[col] = __expf(om - nm);
            rmax[col] = nm;
        }
        __syncthreads();

        // --- pass B: exp + local sums; store V transposed Vt[n][d] ---
        {
            float nm = rmax[col];
            float ls = 0.0f;
#pragma unroll
            for (int n = half * 32; n < half * 32 + 32; n++) {
                float e = __expf(Ps[n * 132 + col] - nm);
                Ps[n * 132 + col] = e;
                ls += e;
            }
            red[half * 128 + col] = ls;
        }
#pragma unroll
        for (int j = 0; j < 4; j++) {
            int idx = tid + j * 256;
            int d = idx >> 4, g = idx & 15;
            KV[(g * 4 + 0) * 68 + d] = vreg[j].x;
            KV[(g * 4 + 1) * 68 + d] = vreg[j].y;
            KV[(g * 4 + 2) * 68 + d] = vreg[j].z;
            KV[(g * 4 + 3) * 68 + d] = vreg[j].w;
        }
        __syncthreads();

        if (tid < 128)
            rsum[col] = rsum[col] * alph[col] + red[col] + red[128 + col];

        // --- rescale accumulators, then PV GEMM ---
        float al[8];
#pragma unroll
        for (int j = 0; j < 8; j++) al[j] = alph[tx * 8 + j];
#pragma unroll
        for (int i = 0; i < 4; i++)
#pragma unroll
            for (int j = 0; j < 8; j++) acc[i][j] *= al[j];

#pragma unroll 8
        for (int n = 0; n < 64; n++) {
            float4 v4 = *(const float4*)&KV[n * 68 + ty * 4];
            float4 p0 = *(const float4*)&Ps[n * 132 + tx * 8];
            float4 p1 = *(const float4*)&Ps[n * 132 + tx * 8 + 4];
            float vd[4] = {v4.x, v4.y, v4.z, v4.w};
            float pm[8] = {p0.x, p0.y, p0.z, p0.w, p1.x, p1.y, p1.z, p1.w};
#pragma unroll
            for (int i = 0; i < 4; i++)
#pragma unroll
                for (int j = 0; j < 8; j++)
                    acc[i][j] += vd[i] * pm[j];
        }
        __syncthreads();  // Ps/KV safe to overwrite next chunk; rsum visible
    }

    // --- epilogue: divide by softmax denominator, write ao[b][h*64+d][n] ---
    float inv[8];
#pragma unroll
    for (int j = 0; j < 8; j++) inv[j] = 1.0f / rsum[tx * 8 + j];

    float* aop = ao + (size_t)bh * 64 * NN_;   // bh*64 == b*512 + h*64
#pragma unroll
    for (int i = 0; i < 4; i++) {
        int d = ty * 4 + i;
        *(float4*)&aop[(size_t)d * NN_ + m0 + tx * 8] =
            make_float4(acc[i][0]*inv[0], acc[i][1]*inv[1], acc[i][2]*inv[2], acc[i][3]*inv[3]);
        *(float4*)&aop[(size_t)d * NN_ + m0 + tx * 8 + 4] =
            make_float4(acc[i][4]*inv[4], acc[i][5]*inv[5], acc[i][6]*inv[6], acc[i][7]*inv[7]);
    }
}

// ---------------------------------------------------------------------------
extern "C" void kernel_launch(void* const* d_in, const int* in_sizes, int n_in,
                              void* d_out, int out_size)
{
    const float* x      = (const float*)d_in[0];  // [8,512,32,32]
    const float* w_qkv  = (const float*)d_in[1];  // [1536,512]
    const float* w_proj = (const float*)d_in[2];  // [512,512]
    const float* b_proj = (const float*)d_in[3];  // [512]
    float* out = (float*)d_out;

    float *qkv_p, *ao_p;
    cudaGetSymbolAddress((void**)&qkv_p, g_qkv);
    cudaGetSymbolAddress((void**)&ao_p,  g_ao);

    cudaFuncSetAttribute(attn_kernel,
                         cudaFuncAttributeMaxDynamicSharedMemorySize,
                         ATTN_SMEM_BYTES);

    // 1) QKV: [1536,512] x [b,512,1024] -> g_qkv
    gemm_kernel<<<dim3(8, 12, 8), 256>>>(w_qkv, x, nullptr, qkv_p, MQKV_);
    // 2) fused attention -> g_ao [b][c][n]
    attn_kernel<<<dim3(8, 64), 256, ATTN_SMEM_BYTES>>>(qkv_p, ao_p);
    // 3) proj: [512,512] x [b,512,1024] + bias -> out
    gemm_kernel<<<dim3(8, 4, 8), 256>>>(w_proj, ao_p, b_proj, out, C_);
}

// round 2
// speedup vs baseline: 4.9699x; 4.9699x over previous
#include <cuda_runtime.h>
#include <cuda_bf16.h>

#define B_     8
#define C_     512
#define NN_    1024
#define MQKV_  1536
#define SCALE_ 0.125f

// Scratch
__device__ float g_qkv[B_ * MQKV_ * NN_];   // [b][h*192 + t*64 + d][n]
__device__ float g_ao [B_ * C_   * NN_];    // [b][c][n]

// ---------------------------------------------------------------------------
// MMA helpers (m16n8k16 bf16, fp32 accum)
// ---------------------------------------------------------------------------
__device__ __forceinline__ unsigned cvta_s(const void* p) {
    return (unsigned)__cvta_generic_to_shared(p);
}
__device__ __forceinline__ void ldm_x4(unsigned* r, unsigned a) {
    asm volatile("ldmatrix.sync.aligned.m8n8.x4.shared.b16 {%0,%1,%2,%3},[%4];"
        : "=r"(r[0]), "=r"(r[1]), "=r"(r[2]), "=r"(r[3]) : "r"(a));
}
__device__ __forceinline__ void ldm_x4t(unsigned* r, unsigned a) {
    asm volatile("ldmatrix.sync.aligned.m8n8.x4.trans.shared.b16 {%0,%1,%2,%3},[%4];"
        : "=r"(r[0]), "=r"(r[1]), "=r"(r[2]), "=r"(r[3]) : "r"(a));
}
__device__ __forceinline__ void mma16816(float* c, const unsigned* a,
                                         unsigned b0, unsigned b1) {
    asm volatile("mma.sync.aligned.m16n8k16.row.col.f32.bf16.bf16.f32 "
        "{%0,%1,%2,%3},{%4,%5,%6,%7},{%8,%9},{%0,%1,%2,%3};"
        : "+f"(c[0]), "+f"(c[1]), "+f"(c[2]), "+f"(c[3])
        : "r"(a[0]), "r"(a[1]), "r"(a[2]), "r"(a[3]), "r"(b0), "r"(b1));
}
// split fp32 pair -> bf16x2 hi and lo (residual)
__device__ __forceinline__ void split_pack(float a, float b, unsigned& hi, unsigned& lo) {
    __nv_bfloat16 ah = __float2bfloat16(a), bh = __float2bfloat16(b);
    __nv_bfloat162 h = __halves2bfloat162(ah, bh);
    __nv_bfloat162 l = __floats2bfloat162_rn(a - __bfloat162float(ah),
                                             b - __bfloat162float(bh));
    hi = *reinterpret_cast<unsigned*>(&h);
    lo = *reinterpret_cast<unsigned*>(&l);
}
__device__ __forceinline__ void split_store(float a, float b,
                                            __nv_bfloat16* ph, __nv_bfloat16* pl) {
    __nv_bfloat16 ah = __float2bfloat16(a), bh = __float2bfloat16(b);
    *reinterpret_cast<__nv_bfloat162*>(ph) = __halves2bfloat162(ah, bh);
    *reinterpret_cast<__nv_bfloat162*>(pl) =
        __floats2bfloat162_rn(a - __bfloat162float(ah), b - __bfloat162float(bh));
}

// ---------------------------------------------------------------------------
// GEMM: out[b][m][n] = sum_c W[m][c] * X[b][c][n] (+ bias), bf16x3 MMA.
// Block 128x128, 8 warps (2x4), warp tile 64x32, k-chunk 32.
// A smem [m][k] (natural), B smem [k][n] (natural, trans-ldmatrix).
// ---------------------------------------------------------------------------
#define AS_STRIDE 40
#define BS_STRIDE 136

__global__ __launch_bounds__(256, 1)
void gemm_mma(const float* __restrict__ W, const float* __restrict__ X,
              const float* __restrict__ bias, float* __restrict__ out, int M)
{
    __shared__ __align__(16) __nv_bfloat16 Ah[128 * AS_STRIDE];
    __shared__ __align__(16) __nv_bfloat16 Al[128 * AS_STRIDE];
    __shared__ __align__(16) __nv_bfloat16 Bh[32 * BS_STRIDE];
    __shared__ __align__(16) __nv_bfloat16 Bl[32 * BS_STRIDE];

    const int tid = threadIdx.x;
    const int lane = tid & 31, w = tid >> 5;
    const int wm = w >> 2, wn = w & 3;
    const int n0 = blockIdx.x * 128, m0 = blockIdx.y * 128, b = blockIdx.z;
    const float* Xb = X + (size_t)b * C_ * NN_;
    const int sub = lane >> 3, subr = lane & 7;

    float acc[4][4][4];
#pragma unroll
    for (int i = 0; i < 4; i++)
#pragma unroll
        for (int j = 0; j < 4; j++)
#pragma unroll
            for (int k = 0; k < 4; k++) acc[i][j][k] = 0.f;

    for (int c0 = 0; c0 < C_; c0 += 32) {
        __syncthreads();
        // A chunk: W[m0..+128][c0..+32]
#pragma unroll
        for (int j = 0; j < 4; j++) {
            int idx = tid + j * 256;
            int r = idx >> 3, kb = (idx & 7) << 2;
            float4 v = *(const float4*)&W[(size_t)(m0 + r) * C_ + c0 + kb];
            split_store(v.x, v.y, &Ah[r * AS_STRIDE + kb],     &Al[r * AS_STRIDE + kb]);
            split_store(v.z, v.w, &Ah[r * AS_STRIDE + kb + 2], &Al[r * AS_STRIDE + kb + 2]);
        }
        // B chunk: X[c0..+32][n0..+128]
#pragma unroll
        for (int j = 0; j < 4; j++) {
            int idx = tid + j * 256;
            int k = idx >> 5, nb = (idx & 31) << 2;
            float4 v = *(const float4*)&Xb[(size_t)(c0 + k) * NN_ + n0 + nb];
            split_store(v.x, v.y, &Bh[k * BS_STRIDE + nb],     &Bl[k * BS_STRIDE + nb]);
            split_store(v.z, v.w, &Bh[k * BS_STRIDE + nb + 2], &Bl[k * BS_STRIDE + nb + 2]);
        }
        __syncthreads();

#pragma unroll
        for (int ks = 0; ks < 2; ks++) {
            unsigned ah[4][4], al[4][4];
#pragma unroll
            for (int mf = 0; mf < 4; mf++) {
                int row = wm * 64 + mf * 16 + (lane & 15);
                int col = ks * 16 + (lane >> 4) * 8;
                ldm_x4(ah[mf], cvta_s(&Ah[row * AS_STRIDE + col]));
                ldm_x4(al[mf], cvta_s(&Al[row * AS_STRIDE + col]));
            }
            unsigned bhf[4][2], blf[4][2];
#pragma unroll
            for (int np = 0; np < 2; np++) {
                int nf = np * 2;
                int krow = ks * 16 + (sub & 1) * 8 + subr;
                int ncol = wn * 32 + (nf + (sub >> 1)) * 8;
                unsigned t[4];
                ldm_x4t(t, cvta_s(&Bh[krow * BS_STRIDE + ncol]));
                bhf[nf][0] = t[0]; bhf[nf][1] = t[1];
                bhf[nf + 1][0] = t[2]; bhf[nf + 1][1] = t[3];
                ldm_x4t(t, cvta_s(&Bl[krow * BS_STRIDE + ncol]));
                blf[nf][0] = t[0]; blf[nf][1] = t[1];
                blf[nf + 1][0] = t[2]; blf[nf + 1][1] = t[3];
            }
#pragma unroll
            for (int mf = 0; mf < 4; mf++)
#pragma unroll
                for (int nf = 0; nf < 4; nf++) {
                    mma16816(acc[mf][nf], ah[mf], bhf[nf][0], bhf[nf][1]);
                    mma16816(acc[mf][nf], ah[mf], blf[nf][0], blf[nf][1]);
                    mma16816(acc[mf][nf], al[mf], bhf[nf][0], bhf[nf][1]);
                }
        }
    }

    const int g = lane >> 2, tg = lane & 3;
    float* ob = out + (size_t)b * M * NN_;
#pragma unroll
    for (int mf = 0; mf < 4; mf++) {
        int r0 = m0 + wm * 64 + mf * 16 + g;
        int r1 = r0 + 8;
        float bv0 = bias ? bias[r0] : 0.f;
        float bv1 = bias ? bias[r1] : 0.f;
#pragma unroll
        for (int nf = 0; nf < 4; nf++) {
            int cc = n0 + wn * 32 + nf * 8 + tg * 2;
            *(float2*)&ob[(size_t)r0 * NN_ + cc] =
                make_float2(acc[mf][nf][0] + bv0, acc[mf][nf][1] + bv0);
            *(float2*)&ob[(size_t)r1 * NN_ + cc] =
                make_float2(acc[mf][nf][2] + bv1, acc[mf][nf][3] + bv1);
        }
    }
}

// ---------------------------------------------------------------------------
// Fused attention, FA2-style register-resident, bf16x3 MMA.
// Block = (bh, m-tile 128). 8 warps, warp owns 16 query rows.
// Q smem [d][m] (natural), K smem [d][n] (natural), V smem [d][n] (natural).
// S mma: A=Q^T via ldmatrix.trans, B=K via ldmatrix.trans.
// PV mma: A=P (from S regs), B=V^T via plain ldmatrix on [d][n].
// ---------------------------------------------------------------------------
#define QS_STRIDE 136
#define KS_STRIDE 72
#define ATTN_SMEM_BYTES ((2 * 64 * QS_STRIDE + 4 * 64 * KS_STRIDE) * 2)

__global__ __launch_bounds__(256, 1)
void attn_mma(const float* __restrict__ qkv, float* __restrict__ ao)
{
    extern __shared__ __align__(16) __nv_bfloat16 smem_raw[];
    __nv_bfloat16* Qh = smem_raw;
    __nv_bfloat16* Ql = Qh + 64 * QS_STRIDE;
    __nv_bfloat16* Kh = Ql + 64 * QS_STRIDE;
    __nv_bfloat16* Kl = Kh + 64 * KS_STRIDE;
    __nv_bfloat16* Vh = Kl + 64 * KS_STRIDE;
    __nv_bfloat16* Vl = Vh + 64 * KS_STRIDE;
    float* Ot = (float*)smem_raw;   // reused after main loop: [64][132]

    const int tid = threadIdx.x, lane = tid & 31, w = tid >> 5;
    const int m0 = blockIdx.x * 128, bh = blockIdx.y;
    const float* qp = qkv + (size_t)bh * 192 * NN_;
    const float* kp = qp + (size_t)64 * NN_;
    const float* vp = qp + (size_t)128 * NN_;
    const int sub = lane >> 3, subr = lane & 7;

    // Q tile load (scaled + split), natural [d][m]
#pragma unroll
    for (int j = 0; j < 8; j++) {
        int idx = tid + j * 256;
        int d = idx >> 5, mb = (idx & 31) << 2;
        float4 v = *(const float4*)&qp[(size_t)d * NN_ + m0 + mb];
        split_store(v.x * SCALE_, v.y * SCALE_,
                    &Qh[d * QS_STRIDE + mb],     &Ql[d * QS_STRIDE + mb]);
        split_store(v.z * SCALE_, v.w * SCALE_,
                    &Qh[d * QS_STRIDE + mb + 2], &Ql[d * QS_STRIDE + mb + 2]);
    }

    float oacc[8][4] = {};
    float rmax0 = -1e30f, rmax1 = -1e30f, rsum0 = 0.f, rsum1 = 0.f;

    for (int n0 = 0; n0 < NN_; n0 += 64) {
        __syncthreads();
        // K/V chunk load, natural [d][n]
#pragma unroll
        for (int j = 0; j < 4; j++) {
            int idx = tid + j * 256;
            int d = idx >> 4, nb = (idx & 15) << 2;
            float4 kv = *(const float4*)&kp[(size_t)d * NN_ + n0 + nb];
            float4 vv = *(const float4*)&vp[(size_t)d * NN_ + n0 + nb];
            split_store(kv.x, kv.y, &Kh[d * KS_STRIDE + nb],     &Kl[d * KS_STRIDE + nb]);
            split_store(kv.z, kv.w, &Kh[d * KS_STRIDE + nb + 2], &Kl[d * KS_STRIDE + nb + 2]);
            split_store(vv.x, vv.y, &Vh[d * KS_STRIDE + nb],     &Vl[d * KS_STRIDE + nb]);
            split_store(vv.z, vv.w, &Vh[d * KS_STRIDE + nb + 2], &Vl[d * KS_STRIDE + nb + 2]);
        }
        __syncthreads();

        // ---- S = (Q*scale)^T K : rows m (warp-local 16), cols n (64) ----
        float sacc[8][4];
#pragma unroll
        for (int i = 0; i < 8; i++) {
            sacc[i][0] = 0.f; sacc[i][1] = 0.f; sacc[i][2] = 0.f; sacc[i][3] = 0.f;
        }
#pragma unroll
        for (int ks = 0; ks < 4; ks++) {
            unsigned qa[4], qlf[4];
            {
                int drow = ks * 16 + (lane >> 4) * 8 + subr;
                int mcol = w * 16 + ((lane >> 3) & 1) * 8;
                ldm_x4t(qa,  cvta_s(&Qh[drow * QS_STRIDE + mcol]));
                ldm_x4t(qlf, cvta_s(&Ql[drow * QS_STRIDE + mcol]));
            }
#pragma unroll
            for (int np = 0; np < 4; np++) {
                int nf = np * 2;
                int krow = ks * 16 + (sub & 1) * 8 + subr;
                int ncol = (nf + (sub >> 1)) * 8;
                unsigned th[4], tl[4];
                ldm_x4t(th, cvta_s(&Kh[krow * KS_STRIDE + ncol]));
                ldm_x4t(tl, cvta_s(&Kl[krow * KS_STRIDE + ncol]));
                mma16816(sacc[nf],     qa,  th[0], th[1]);
                mma16816(sacc[nf],     qa,  tl[0], tl[1]);
                mma16816(sacc[nf],     qlf, th[0], th[1]);
                mma16816(sacc[nf + 1], qa,  th[2], th[3]);
                mma16816(sacc[nf + 1], qa,  tl[2], tl[3]);
                mma16816(sacc[nf + 1], qlf, th[2], th[3]);
            }
        }

        // ---- online softmax over n (chunk), per row (quad-local) ----
        float cm0 = -1e30f, cm1 = -1e30f;
#pragma unroll
        for (int nf = 0; nf < 8; nf++) {
            cm0 = fmaxf(cm0, fmaxf(sacc[nf][0], sacc[nf][1]));
            cm1 = fmaxf(cm1, fmaxf(sacc[nf][2], sacc[nf][3]));
        }
        cm0 = fmaxf(cm0, __shfl_xor_sync(0xffffffffu, cm0, 1));
        cm0 = fmaxf(cm0, __shfl_xor_sync(0xffffffffu, cm0, 2));
        cm1 = fmaxf(cm1, __shfl_xor_sync(0xffffffffu, cm1, 1));
        cm1 = fmaxf(cm1, __shfl_xor_sync(0xffffffffu, cm1, 2));
        float nm0 = fmaxf(rmax0, cm0), nm1 = fmaxf(rmax1, cm1);
        float a0 = __expf(rmax0 - nm0), a1 = __expf(rmax1 - nm1);
        rmax0 = nm0; rmax1 = nm1;

        float ps0 = 0.f, ps1 = 0.f;
#pragma unroll
        for (int nf = 0; nf < 8; nf++) {
            sacc[nf][0] = __expf(sacc[nf][0] - nm0);
            sacc[nf][1] = __expf(sacc[nf][1] - nm0);
            sacc[nf][2] = __expf(sacc[nf][2] - nm1);
            sacc[nf][3] = __expf(sacc[nf][3] - nm1);
            ps0 += sacc[nf][0] + sacc[nf][1];
            ps1 += sacc[nf][2] + sacc[nf][3];
        }
        ps0 += __shfl_xor_sync(0xffffffffu, ps0, 1);
        ps0 += __shfl_xor_sync(0xffffffffu, ps0, 2);
        ps1 += __shfl_xor_sync(0xffffffffu, ps1, 1);
        ps1 += __shfl_xor_sync(0xffffffffu, ps1, 2);
        rsum0 = rsum0 * a0 + ps0;
        rsum1 = rsum1 * a1 + ps1;

#pragma unroll
        for (int df = 0; df < 8; df++) {
            oacc[df][0] *= a0; oacc[df][1] *= a0;
            oacc[df][2] *= a1; oacc[df][3] *= a1;
        }

        // ---- PV: out[m][d] += P[m][n] V^T[n][d]; P from sacc registers ----
#pragma unroll
        for (int ks = 0; ks < 4; ks++) {
            unsigned ph[4], pl[4];
            split_pack(sacc[2 * ks][0],     sacc[2 * ks][1],     ph[0], pl[0]);
            split_pack(sacc[2 * ks][2],     sacc[2 * ks][3],     ph[1], pl[1]);
            split_pack(sacc[2 * ks + 1][0], sacc[2 * ks + 1][1], ph[2], pl[2]);
            split_pack(sacc[2 * ks + 1][2], sacc[2 * ks + 1][3], ph[3], pl[3]);
#pragma unroll
            for (int dp = 0; dp < 4; dp++) {
                int df = dp * 2;
                int drow = (df + (sub >> 1)) * 8 + subr;
                int col = ks * 16 + (sub & 1) * 8;
                unsigned th[4], tl[4];
                ldm_x4(th, cvta_s(&Vh[drow * KS_STRIDE + col]));
                ldm_x4(tl, cvta_s(&Vl[drow * KS_STRIDE + col]));
                mma16816(oacc[df],     ph, th[0], th[1]);
                mma16816(oacc[df],     ph, tl[0], tl[1]);
                mma16816(oacc[df],     pl, th[0], th[1]);
                mma16816(oacc[df + 1], ph, th[2], th[3]);
                mma16816(oacc[df + 1], ph, tl[2], tl[3]);
                mma16816(oacc[df + 1], pl, th[2], th[3]);
            }
        }
    }

    __syncthreads();   // everyone done reading Q/K/V smem
    // Normalize + transpose via smem bounce: Ot[d][m]
    const int g = lane >> 2, tg = lane & 3;
    float i0 = 1.f / rsum0, i1 = 1.f / rsum1;
#pragma unroll
    for (int df = 0; df < 8; df++) {
        int d = df * 8 + tg * 2;
        int mr = w * 16 + g;
        Ot[(d    ) * 132 + mr    ] = oacc[df][0] * i0;
        Ot[(d + 1) * 132 + mr    ] = oacc[df][1] * i0;
        Ot[(d    ) * 132 + mr + 8] = oacc[df][2] * i1;
        Ot[(d + 1) * 132 + mr + 8] = oacc[df][3] * i1;
    }
    __syncthreads();
#pragma unroll
    for (int j = 0; j < 8; j++) {
        int idx = tid + j * 256;
        int d = idx >> 5, mb = (idx & 31) << 2;
        float4 v = *(const float4*)&Ot[d * 132 + mb];
        *(float4*)&ao[(size_t)(bh * 64 + d) * NN_ + m0 + mb] = v;
    }
}

// ---------------------------------------------------------------------------
extern "C" void kernel_launch(void* const* d_in, const int* in_sizes, int n_in,
                              void* d_out, int out_size)
{
    const float* x      = (const float*)d_in[0];
    const float* w_qkv  = (const float*)d_in[1];
    const float* w_proj = (const float*)d_in[2];
    const float* b_proj = (const float*)d_in[3];
    float* out = (float*)d_out;

    float *qkv_p, *ao_p;
    cudaGetSymbolAddress((void**)&qkv_p, g_qkv);
    cudaGetSymbolAddress((void**)&ao_p,  g_ao);

    cudaFuncSetAttribute(attn_mma,
                         cudaFuncAttributeMaxDynamicSharedMemorySize,
                         ATTN_SMEM_BYTES);

    gemm_mma<<<dim3(8, 12, 8), 256>>>(w_qkv, x, nullptr, qkv_p, MQKV_);
    attn_mma<<<dim3(8, 64), 256, ATTN_SMEM_BYTES>>>(qkv_p, ao_p);
    gemm_mma<<<dim3(8, 4, 8), 256>>>(w_proj, ao_p, b_proj, out, C_);
}

// round 4
// speedup vs baseline: 5.2621x; 1.0588x over previous
#include <cuda_runtime.h>
#include <cuda_bf16.h>

#define B_     8
#define C_     512
#define NN_    1024
#define MQKV_  1536
#define SCALE_ 0.125f

// ---------------------------------------------------------------------------
// Scratch: presplit bf16 hi/lo arrays
// ---------------------------------------------------------------------------
__device__ __nv_bfloat16 g_xh [B_ * C_ * NN_];
__device__ __nv_bfloat16 g_xl [B_ * C_ * NN_];
__device__ __nv_bfloat16 g_wqh[MQKV_ * C_];
__device__ __nv_bfloat16 g_wql[MQKV_ * C_];
__device__ __nv_bfloat16 g_wph[C_ * C_];
__device__ __nv_bfloat16 g_wpl[C_ * C_];
__device__ __nv_bfloat16 g_qkvh[B_ * MQKV_ * NN_];
__device__ __nv_bfloat16 g_qkvl[B_ * MQKV_ * NN_];
__device__ __nv_bfloat16 g_aoh[B_ * C_ * NN_];
__device__ __nv_bfloat16 g_aol[B_ * C_ * NN_];

// ---------------------------------------------------------------------------
// helpers
// ---------------------------------------------------------------------------
__device__ __forceinline__ unsigned cvta_s(const void* p) {
    return (unsigned)__cvta_generic_to_shared(p);
}
__device__ __forceinline__ void ldm_x4(unsigned* r, unsigned a) {
    asm volatile("ldmatrix.sync.aligned.m8n8.x4.shared.b16 {%0,%1,%2,%3},[%4];"
        : "=r"(r[0]), "=r"(r[1]), "=r"(r[2]), "=r"(r[3]) : "r"(a));
}
__device__ __forceinline__ void ldm_x4t(unsigned* r, unsigned a) {
    asm volatile("ldmatrix.sync.aligned.m8n8.x4.trans.shared.b16 {%0,%1,%2,%3},[%4];"
        : "=r"(r[0]), "=r"(r[1]), "=r"(r[2]), "=r"(r[3]) : "r"(a));
}
__device__ __forceinline__ void mma16816(float* c, const unsigned* a,
                                         unsigned b0, unsigned b1) {
    asm volatile("mma.sync.aligned.m16n8k16.row.col.f32.bf16.bf16.f32 "
        "{%0,%1,%2,%3},{%4,%5,%6,%7},{%8,%9},{%0,%1,%2,%3};"
        : "+f"(c[0]), "+f"(c[1]), "+f"(c[2]), "+f"(c[3])
        : "r"(a[0]), "r"(a[1]), "r"(a[2]), "r"(a[3]), "r"(b0), "r"(b1));
}
__device__ __forceinline__ void cp16(void* s, const void* g) {
    asm volatile("cp.async.cg.shared.global [%0],[%1],16;"
        :: "r"(cvta_s(s)), "l"(g));
}
__device__ __forceinline__ void cp_commit() {
    asm volatile("cp.async.commit_group;");
}
template<int N> __device__ __forceinline__ void cp_wait() {
    asm volatile("cp.async.wait_group %0;" :: "n"(N));
}
__device__ __forceinline__ void split_pack(float a, float b, unsigned& hi, unsigned& lo) {
    __nv_bfloat16 ah = __float2bfloat16(a), bh = __float2bfloat16(b);
    __nv_bfloat162 h = __halves2bfloat162(ah, bh);
    __nv_bfloat162 l = __floats2bfloat162_rn(a - __bfloat162float(ah),
                                             b - __bfloat162float(bh));
    hi = *reinterpret_cast<unsigned*>(&h);
    lo = *reinterpret_cast<unsigned*>(&l);
}
__device__ __forceinline__ void split_store(float a, float b,
                                            __nv_bfloat16* ph, __nv_bfloat16* pl) {
    __nv_bfloat16 ah = __float2bfloat16(a), bh = __float2bfloat16(b);
    *reinterpret_cast<__nv_bfloat162*>(ph) = __halves2bfloat162(ah, bh);
    *reinterpret_cast<__nv_bfloat162*>(pl) =
        __floats2bfloat162_rn(a - __bfloat162float(ah), b - __bfloat162float(bh));
}

// ---------------------------------------------------------------------------
// Elementwise fp32 -> bf16 hi/lo split
// ---------------------------------------------------------------------------
__global__ void split_f32(const float* __restrict__ src,
                          __nv_bfloat16* __restrict__ h,
                          __nv_bfloat16* __restrict__ l, int n4)
{
    int i = blockIdx.x * blockDim.x + threadIdx.x;
    if (i < n4) {
        float4 v = ((const float4*)src)[i];
        split_store(v.x, v.y, h + i * 4,     l + i * 4);
        split_store(v.z, v.w, h + i * 4 + 2, l + i * 4 + 2);
    }
}

// ---------------------------------------------------------------------------
// GEMM on presplit bf16: out = A * B (+bias).  A [M][512] row-major hi/lo,
// B [b][512][1024] hi/lo.  Block 128x128, k-chunk 32, 8 warps (2x4),
// cp.async 2-stage double buffer.
// SPLIT_OUT=1: write bf16 hi/lo (qkv).  SPLIT_OUT=0: write fp32 + bias.
// ---------------------------------------------------------------------------
#define AS_STRIDE 40
#define BS_STRIDE 136
#define A_STG (128 * AS_STRIDE)
#define B_STG (32 * BS_STRIDE)
#define G_STG (2 * A_STG + 2 * B_STG)          // elems per stage
#define GEMM_SMEM_BYTES (2 * G_STG * 2)

template<int SPLIT_OUT>
__global__ __launch_bounds__(256)
void gemm_mma(const __nv_bfloat16* __restrict__ Ah_g,
              const __nv_bfloat16* __restrict__ Al_g,
              const __nv_bfloat16* __restrict__ Bh_g,
              const __nv_bfloat16* __restrict__ Bl_g,
              const float* __restrict__ bias,
              float* __restrict__ out,
              __nv_bfloat16* __restrict__ outh,
              __nv_bfloat16* __restrict__ outl, int M)
{
    extern __shared__ __align__(16) __nv_bfloat16 sm[];

    const int tid = threadIdx.x;
    const int lane = tid & 31, w = tid >> 5;
    const int wm = w >> 2, wn = w & 3;
    const int n0 = blockIdx.x * 128, m0 = blockIdx.y * 128, b = blockIdx.z;
    const __nv_bfloat16* Bh_b = Bh_g + (size_t)b * C_ * NN_;
    const __nv_bfloat16* Bl_b = Bl_g + (size_t)b * C_ * NN_;
    const int sub = lane >> 3, subr = lane & 7;

    __nv_bfloat16* Ah_s[2]; __nv_bfloat16* Al_s[2];
    __nv_bfloat16* Bh_s[2]; __nv_bfloat16* Bl_s[2];
#pragma unroll
    for (int s = 0; s < 2; s++) {
        __nv_bfloat16* base = sm + s * G_STG;
        Ah_s[s] = base;
        Al_s[s] = base + A_STG;
        Bh_s[s] = base + 2 * A_STG;
        Bl_s[s] = base + 2 * A_STG + B_STG;
    }

    // per-thread load coords
    const int a_r = tid >> 2,  a_seg = (tid & 3) * 8;     // rows 0..63 (+64), 4 segs
    const int b_k = tid >> 4,  b_seg = (tid & 15) * 8;    // k 0..15 (+16), 16 segs

    auto prefetch = [&](int chunk, int s) {
        int c0 = chunk * 32;
#pragma unroll
        for (int j = 0; j < 2; j++) {
            int r = a_r + j * 64;
            const size_t go = (size_t)(m0 + r) * C_ + c0 + a_seg;
            cp16(&Ah_s[s][r * AS_STRIDE + a_seg], Ah_g + go);
            cp16(&Al_s[s][r * AS_STRIDE + a_seg], Al_g + go);
        }
#pragma unroll
        for (int j = 0; j < 2; j++) {
            int k = b_k + j * 16;
            const size_t go = (size_t)(c0 + k) * NN_ + n0 + b_seg;
            cp16(&Bh_s[s][k * BS_STRIDE + b_seg], Bh_b + go);
            cp16(&Bl_s[s][k * BS_STRIDE + b_seg], Bl_b + go);
        }
    };

    float acc[4][4][4];
#pragma unroll
    for (int i = 0; i < 4; i++)
#pragma unroll
        for (int j = 0; j < 4; j++)
#pragma unroll
            for (int k = 0; k < 4; k++) acc[i][j][k] = 0.f;

    prefetch(0, 0);
    cp_commit();

    for (int ch = 0; ch < 16; ch++) {
        int s = ch & 1;
        if (ch < 15) { prefetch(ch + 1, s ^ 1); cp_commit(); cp_wait<1>(); }
        else         { cp_wait<0>(); }
        __syncthreads();

#pragma unroll
        for (int ks = 0; ks < 2; ks++) {
            unsigned ah[4][4], al[4][4];
#pragma unroll
            for (int mf = 0; mf < 4; mf++) {
                int row = wm * 64 + mf * 16 + (lane & 15);
                int col = ks * 16 + (lane >> 4) * 8;
                ldm_x4(ah[mf], cvta_s(&Ah_s[s][row * AS_STRIDE + col]));
                ldm_x4(al[mf], cvta_s(&Al_s[s][row * AS_STRIDE + col]));
            }
            unsigned bhf[4][2], blf[4][2];
#pragma unroll
            for (int np = 0; np < 2; np++) {
                int nf = np * 2;
                int krow = ks * 16 + (sub & 1) * 8 + subr;
                int ncol = wn * 32 + (nf + (sub >> 1)) * 8;
                unsigned t[4];
                ldm_x4t(t, cvta_s(&Bh_s[s][krow * BS_STRIDE + ncol]));
                bhf[nf][0] = t[0]; bhf[nf][1] = t[1];
                bhf[nf + 1][0] = t[2]; bhf[nf + 1][1] = t[3];
                ldm_x4t(t, cvta_s(&Bl_s[s][krow * BS_STRIDE + ncol]));
                blf[nf][0] = t[0]; blf[nf][1] = t[1];
                blf[nf + 1][0] = t[2]; blf[nf + 1][1] = t[3];
            }
#pragma unroll
            for (int mf = 0; mf < 4; mf++)
#pragma unroll
                for (int nf = 0; nf < 4; nf++) {
                    mma16816(acc[mf][nf], ah[mf], bhf[nf][0], bhf[nf][1]);
                    mma16816(acc[mf][nf], ah[mf], blf[nf][0], blf[nf][1]);
                    mma16816(acc[mf][nf], al[mf], bhf[nf][0], bhf[nf][1]);
                }
        }
        __syncthreads();
    }

    const int g = lane >> 2, tg = lane & 3;
#pragma unroll
    for (int mf = 0; mf < 4; mf++) {
        int r0 = m0 + wm * 64 + mf * 16 + g;
        int r1 = r0 + 8;
        if (SPLIT_OUT) {
            __nv_bfloat16* oh = outh + (size_t)b * M * NN_;
            __nv_bfloat16* ol = outl + (size_t)b * M * NN_;
#pragma unroll
            for (int nf = 0; nf < 4; nf++) {
                int cc = n0 + wn * 32 + nf * 8 + tg * 2;
                split_store(acc[mf][nf][0], acc[mf][nf][1],
                            &oh[(size_t)r0 * NN_ + cc], &ol[(size_t)r0 * NN_ + cc]);
                split_store(acc[mf][nf][2], acc[mf][nf][3],
                            &oh[(size_t)r1 * NN_ + cc], &ol[(size_t)r1 * NN_ + cc]);
            }
        } else {
            float* ob = out + (size_t)b * M * NN_;
            float bv0 = bias[r0], bv1 = bias[r1];
#pragma unroll
            for (int nf = 0; nf < 4; nf++) {
                int cc = n0 + wn * 32 + nf * 8 + tg * 2;
                *(float2*)&ob[(size_t)r0 * NN_ + cc] =
                    make_float2(acc[mf][nf][0] + bv0, acc[mf][nf][1] + bv0);
                *(float2*)&ob[(size_t)r1 * NN_ + cc] =
                    make_float2(acc[mf][nf][2] + bv1, acc[mf][nf][3] + bv1);
            }
        }
    }
}

// ---------------------------------------------------------------------------
// Fused attention on presplit bf16 qkv.  FA2 register-resident, bf16x3 MMA.
// cp.async 2-stage K/V pipeline.  Output written split bf16 (hi/lo).
// ---------------------------------------------------------------------------
#define QS_STRIDE 136
#define KS_STRIDE 72
#define Q_ELEMS  (64 * QS_STRIDE)
#define KV_ARR   (64 * KS_STRIDE)
#define KV_STG   (4 * KV_ARR)
#define ATTN_SMEM_BYTES ((2 * Q_ELEMS + 2 * KV_STG) * 2)

__global__ __launch_bounds__(256)
void attn_mma(const __nv_bfloat16* __restrict__ qkvh,
              const __nv_bfloat16* __restrict__ qkvl,
              __nv_bfloat16* __restrict__ aoh,
              __nv_bfloat16* __restrict__ aol)
{
    extern __shared__ __align__(16) __nv_bfloat16 sm[];
    __nv_bfloat16* Qh = sm;
    __nv_bfloat16* Ql = Qh + Q_ELEMS;
    __nv_bfloat16* KVs = Ql + Q_ELEMS;   // [2 stages][Kh|Kl|Vh|Vl]
    float* Ot = (float*)sm;              // epilogue reuse [64][132]

    const int tid = threadIdx.x, lane = tid & 31, w = tid >> 5;
    const int m0 = blockIdx.x * 128, bh = blockIdx.y;
    const size_t base = (size_t)bh * 192 * NN_;
    const __nv_bfloat16* qh = qkvh + base;
    const __nv_bfloat16* ql = qkvl + base;
    const __nv_bfloat16* kh = qh + (size_t)64 * NN_;
    const __nv_bfloat16* kl = ql + (size_t)64 * NN_;
    const __nv_bfloat16* vh = qh + (size_t)128 * NN_;
    const __nv_bfloat16* vl = ql + (size_t)128 * NN_;
    const int sub = lane >> 3, subr = lane & 7;

    // Q loads: [d=64][m=128] -> 16 segs of 16B per row per array
    {
        const int d = tid >> 4, seg = (tid & 15) * 8;
#pragma unroll
        for (int j = 0; j < 4; j++) {
            int dd = d + j * 16;
            const size_t go = (size_t)dd * NN_ + m0 + seg;
            cp16(&Qh[dd * QS_STRIDE + seg], qh + go);
            cp16(&Ql[dd * QS_STRIDE + seg], ql + go);
        }
    }
    // KV prefetch: [d=64][n0..+64] -> 8 segs of 16B per row per array.
    // 256 threads cover d in [0,32); j loop covers the second d-half.
    const int kv_d = tid >> 3, kv_seg = (tid & 7) * 8;
    auto kv_prefetch = [&](int chunk, int s) {
        __nv_bfloat16* st = KVs + s * KV_STG;
        int n0 = chunk * 64;
#pragma unroll
        for (int j = 0; j < 2; j++) {
            int dd = kv_d + j * 32;
            const size_t go = (size_t)dd * NN_ + n0 + kv_seg;
            const int so = dd * KS_STRIDE + kv_seg;
            cp16(&st[so],              kh + go);
            cp16(&st[KV_ARR + so],     kl + go);
            cp16(&st[2 * KV_ARR + so], vh + go);
            cp16(&st[3 * KV_ARR + so], vl + go);
        }
    };

    kv_prefetch(0, 0);
    cp_commit();

    float oacc[8][4] = {};
    float rmax0 = -1e30f, rmax1 = -1e30f, rsum0 = 0.f, rsum1 = 0.f;

    for (int ch = 0; ch < 16; ch++) {
        int s = ch & 1;
        if (ch < 15) { kv_prefetch(ch + 1, s ^ 1); cp_commit(); cp_wait<1>(); }
        else         { cp_wait<0>(); }
        __syncthreads();

        __nv_bfloat16* Kh_s = KVs + s * KV_STG;
        __nv_bfloat16* Kl_s = Kh_s + KV_ARR;
        __nv_bfloat16* Vh_s = Kh_s + 2 * KV_ARR;
        __nv_bfloat16* Vl_s = Kh_s + 3 * KV_ARR;

        // ---- S = Q^T K ----
        float sacc[8][4];
#pragma unroll
        for (int i = 0; i < 8; i++) {
            sacc[i][0] = 0.f; sacc[i][1] = 0.f; sacc[i][2] = 0.f; sacc[i][3] = 0.f;
        }
#pragma unroll
        for (int ks = 0; ks < 4; ks++) {
            unsigned qa[4], qlf[4];
            {
                int drow = ks * 16 + (lane >> 4) * 8 + subr;
                int mcol = w * 16 + ((lane >> 3) & 1) * 8;
                ldm_x4t(qa,  cvta_s(&Qh[drow * QS_STRIDE + mcol]));
                ldm_x4t(qlf, cvta_s(&Ql[drow * QS_STRIDE + mcol]));
            }
#pragma unroll
            for (int np = 0; np < 4; np++) {
                int nf = np * 2;
                int krow = ks * 16 + (sub & 1) * 8 + subr;
                int ncol = (nf + (sub >> 1)) * 8;
                unsigned th[4], tl[4];
                ldm_x4t(th, cvta_s(&Kh_s[krow * KS_STRIDE + ncol]));
                ldm_x4t(tl, cvta_s(&Kl_s[krow * KS_STRIDE + ncol]));
                mma16816(sacc[nf],     qa,  th[0], th[1]);
                mma16816(sacc[nf],     qa,  tl[0], tl[1]);
                mma16816(sacc[nf],     qlf, th[0], th[1]);
                mma16816(sacc[nf + 1], qa,  th[2], th[3]);
                mma16816(sacc[nf + 1], qa,  tl[2], tl[3]);
                mma16816(sacc[nf + 1], qlf, th[2], th[3]);
            }
        }
        // apply scale (exact: 2^-3)
#pragma unroll
        for (int nf = 0; nf < 8; nf++) {
            sacc[nf][0] *= SCALE_; sacc[nf][1] *= SCALE_;
            sacc[nf][2] *= SCALE_; sacc[nf][3] *= SCALE_;
        }

        // ---- online softmax (rows are quad-local) ----
        float cm0 = -1e30f, cm1 = -1e30f;
#pragma unroll
        for (int nf = 0; nf < 8; nf++) {
            cm0 = fmaxf(cm0, fmaxf(sacc[nf][0], sacc[nf][1]));
            cm1 = fmaxf(cm1, fmaxf(sacc[nf][2], sacc[nf][3]));
        }
        cm0 = fmaxf(cm0, __shfl_xor_sync(0xffffffffu, cm0, 1));
        cm0 = fmaxf(cm0, __shfl_xor_sync(0xffffffffu, cm0, 2));
        cm1 = fmaxf(cm1, __shfl_xor_sync(0xffffffffu, cm1, 1));
        cm1 = fmaxf(cm1, __shfl_xor_sync(0xffffffffu, cm1, 2));
        float nm0 = fmaxf(rmax0, cm0), nm1 = fmaxf(rmax1, cm1);
        float a0 = __expf(rmax0 - nm0), a1 = __expf(rmax1 - nm1);
        rmax0 = nm0; rmax1 = nm1;

        float ps0 = 0.f, ps1 = 0.f;
#pragma unroll
        for (int nf = 0; nf < 8; nf++) {
            sacc[nf][0] = __expf(sacc[nf][0] - nm0);
            sacc[nf][1] = __expf(sacc[nf][1] - nm0);
            sacc[nf][2] = __expf(sacc[nf][2] - nm1);
            sacc[nf][3] = __expf(sacc[nf][3] - nm1);
            ps0 += sacc[nf][0] + sacc[nf][1];
            ps1 += sacc[nf][2] + sacc[nf][3];
        }
        ps0 += __shfl_xor_sync(0xffffffffu, ps0, 1);
        ps0 += __shfl_xor_sync(0xffffffffu, ps0, 2);
        ps1 += __shfl_xor_sync(0xffffffffu, ps1, 1);
        ps1 += __shfl_xor_sync(0xffffffffu, ps1, 2);
        rsum0 = rsum0 * a0 + ps0;
        rsum1 = rsum1 * a1 + ps1;

#pragma unroll
        for (int df = 0; df < 8; df++) {
            oacc[df][0] *= a0; oacc[df][1] *= a0;
            oacc[df][2] *= a1; oacc[df][3] *= a1;
        }

        // ---- PV ----
#pragma unroll
        for (int ks = 0; ks < 4; ks++) {
            unsigned ph[4], pl[4];
            split_pack(sacc[2 * ks][0],     sacc[2 * ks][1],     ph[0], pl[0]);
            split_pack(sacc[2 * ks][2],     sacc[2 * ks][3],     ph[1], pl[1]);
            split_pack(sacc[2 * ks + 1][0], sacc[2 * ks + 1][1], ph[2], pl[2]);
            split_pack(sacc[2 * ks + 1][2], sacc[2 * ks + 1][3], ph[3], pl[3]);
#pragma unroll
            for (int dp = 0; dp < 4; dp++) {
                int df = dp * 2;
                int drow = (df + (sub >> 1)) * 8 + subr;
                int col = ks * 16 + (sub & 1) * 8;
                unsigned th[4], tl[4];
                ldm_x4(th, cvta_s(&Vh_s[drow * KS_STRIDE + col]));
                ldm_x4(tl, cvta_s(&Vl_s[drow * KS_STRIDE + col]));
                mma16816(oacc[df],     ph, th[0], th[1]);
                mma16816(oacc[df],     ph, tl[0], tl[1]);
                mma16816(oacc[df],     pl, th[0], th[1]);
                mma16816(oacc[df + 1], ph, th[2], th[3]);
                mma16816(oacc[df + 1], ph, tl[2], tl[3]);
                mma16816(oacc[df + 1], pl, th[2], th[3]);
            }
        }
        __syncthreads();
    }

    // ---- epilogue: normalize, transpose via smem, split-store ----
    const int g = lane >> 2, tg = lane & 3;
    float i0 = 1.f / rsum0, i1 = 1.f / rsum1;
#pragma unroll
    for (int df = 0; df < 8; df++) {
        int d = df * 8 + tg * 2;
        int mr = w * 16 + g;
        Ot[(d    ) * 132 + mr    ] = oacc[df][0] * i0;
        Ot[(d + 1) * 132 + mr    ] = oacc[df][1] * i0;
        Ot[(d    ) * 132 + mr + 8] = oacc[df][2] * i1;
        Ot[(d + 1) * 132 + mr + 8] = oacc[df][3] * i1;
    }
    __syncthreads();
#pragma unroll
    for (int j = 0; j < 8; j++) {
        int idx = tid + j * 256;
        int d = idx >> 5, mb = (idx & 31) << 2;
        float4 v = *(const float4*)&Ot[d * 132 + mb];
        size_t go = (size_t)(bh * 64 + d) * NN_ + m0 + mb;
        split_store(v.x, v.y, aoh + go,     aol + go);
        split_store(v.z, v.w, aoh + go + 2, aol + go + 2);
    }
}

// ---------------------------------------------------------------------------
extern "C" void kernel_launch(void* const* d_in, const int* in_sizes, int n_in,
                              void* d_out, int out_size)
{
    const float* x      = (const float*)d_in[0];
    const float* w_qkv  = (const float*)d_in[1];
    const float* w_proj = (const float*)d_in[2];
    const float* b_proj = (const float*)d_in[3];
    float* out = (float*)d_out;

    __nv_bfloat16 *xh, *xl, *wqh, *wql, *wph, *wpl, *qkvh, *qkvl, *aoh, *aol;
    cudaGetSymbolAddress((void**)&xh,  g_xh);  cudaGetSymbolAddress((void**)&xl,  g_xl);
    cudaGetSymbolAddress((void**)&wqh, g_wqh); cudaGetSymbolAddress((void**)&wql, g_wql);
    cudaGetSymbolAddress((void**)&wph, g_wph); cudaGetSymbolAddress((void**)&wpl, g_wpl);
    cudaGetSymbolAddress((void**)&qkvh, g_qkvh); cudaGetSymbolAddress((void**)&qkvl, g_qkvl);
    cudaGetSymbolAddress((void**)&aoh, g_aoh); cudaGetSymbolAddress((void**)&aol, g_aol);

    cudaFuncSetAttribute(gemm_mma<1>,
        cudaFuncAttributeMaxDynamicSharedMemorySize, GEMM_SMEM_BYTES);
    cudaFuncSetAttribute(gemm_mma<0>,
        cudaFuncAttributeMaxDynamicSharedMemorySize, GEMM_SMEM_BYTES);
    cudaFuncSetAttribute(attn_mma,
        cudaFuncAttributeMaxDynamicSharedMemorySize, ATTN_SMEM_BYTES);

    // 0) presplit inputs
    split_f32<<<(B_ * C_ * NN_ / 4 + 255) / 256, 256>>>(x, xh, xl, B_ * C_ * NN_ / 4);
    split_f32<<<(MQKV_ * C_ / 4 + 255) / 256, 256>>>(w_qkv, wqh, wql, MQKV_ * C_ / 4);
    split_f32<<<(C_ * C_ / 4 + 255) / 256, 256>>>(w_proj, wph, wpl, C_ * C_ / 4);

    // 1) QKV GEMM -> split qkv
    gemm_mma<1><<<dim3(8, 12, 8), 256, GEMM_SMEM_BYTES>>>(
        wqh, wql, xh, xl, nullptr, nullptr, qkvh, qkvl, MQKV_);
    // 2) attention -> split ao
    attn_mma<<<dim3(8, 64), 256, ATTN_SMEM_BYTES>>>(qkvh, qkvl, aoh, aol);
    // 3) proj GEMM -> fp32 out (+bias)
    gemm_mma<0><<<dim3(8, 4, 8), 256, GEMM_SMEM_BYTES>>>(
        wph, wpl, aoh, aol, b_proj, out, nullptr, nullptr, C_);
}

// round 6
// speedup vs baseline: 7.1722x; 1.3630x over previous
#include <cuda_runtime.h>
#include <cuda_fp16.h>

#define B_     8
#define C_     512
#define NN_    1024
#define MQKV_  1536
#define SCALE_ 0.125f

// ---------------------------------------------------------------------------
// Scratch: fp16 operands.  A-side (weights / Q / P) single fp16; B-side split.
// ---------------------------------------------------------------------------
__device__ __half g_xh [B_ * C_ * NN_];
__device__ __half g_xl [B_ * C_ * NN_];
__device__ __half g_wq [MQKV_ * C_];
__device__ __half g_wp [C_ * C_];
__device__ __half g_qkvh[B_ * MQKV_ * NN_];
__device__ __half g_qkvl[B_ * MQKV_ * NN_];
__device__ __half g_aoh[B_ * C_ * NN_];
__device__ __half g_aol[B_ * C_ * NN_];

// ---------------------------------------------------------------------------
// helpers
// ---------------------------------------------------------------------------
__device__ __forceinline__ unsigned cvta_s(const void* p) {
    return (unsigned)__cvta_generic_to_shared(p);
}
__device__ __forceinline__ void ldm_x4(unsigned* r, unsigned a) {
    asm volatile("ldmatrix.sync.aligned.m8n8.x4.shared.b16 {%0,%1,%2,%3},[%4];"
        : "=r"(r[0]), "=r"(r[1]), "=r"(r[2]), "=r"(r[3]) : "r"(a));
}
__device__ __forceinline__ void ldm_x4t(unsigned* r, unsigned a) {
    asm volatile("ldmatrix.sync.aligned.m8n8.x4.trans.shared.b16 {%0,%1,%2,%3},[%4];"
        : "=r"(r[0]), "=r"(r[1]), "=r"(r[2]), "=r"(r[3]) : "r"(a));
}
__device__ __forceinline__ void mma16816(float* c, const unsigned* a,
                                         unsigned b0, unsigned b1) {
    asm volatile("mma.sync.aligned.m16n8k16.row.col.f32.f16.f16.f32 "
        "{%0,%1,%2,%3},{%4,%5,%6,%7},{%8,%9},{%0,%1,%2,%3};"
        : "+f"(c[0]), "+f"(c[1]), "+f"(c[2]), "+f"(c[3])
        : "r"(a[0]), "r"(a[1]), "r"(a[2]), "r"(a[3]), "r"(b0), "r"(b1));
}
__device__ __forceinline__ void cp16(void* s, const void* g) {
    asm volatile("cp.async.cg.shared.global [%0],[%1],16;"
        :: "r"(cvta_s(s)), "l"(g));
}
__device__ __forceinline__ void cp_commit() {
    asm volatile("cp.async.commit_group;");
}
template<int N> __device__ __forceinline__ void cp_wait() {
    asm volatile("cp.async.wait_group %0;" :: "n"(N));
}
__device__ __forceinline__ unsigned pack_h(float a, float b) {
    __half2 h = __floats2half2_rn(a, b);
    return *reinterpret_cast<unsigned*>(&h);
}
__device__ __forceinline__ void split_store_h(float a, float b,
                                              __half* ph, __half* pl) {
    __half ah = __float2half_rn(a), bh = __float2half_rn(b);
    *reinterpret_cast<__half2*>(ph) = __halves2half2(ah, bh);
    *reinterpret_cast<__half2*>(pl) =
        __floats2half2_rn(a - __half2float(ah), b - __half2float(bh));
}

// ---------------------------------------------------------------------------
// Conversion kernels
// ---------------------------------------------------------------------------
__global__ void split_f32h(const float* __restrict__ src,
                           __half* __restrict__ h, __half* __restrict__ l, int n4)
{
    int i = blockIdx.x * blockDim.x + threadIdx.x;
    if (i < n4) {
        float4 v = ((const float4*)src)[i];
        split_store_h(v.x, v.y, h + i * 4,     l + i * 4);
        split_store_h(v.z, v.w, h + i * 4 + 2, l + i * 4 + 2);
    }
}
__global__ void conv_f32h(const float* __restrict__ src,
                          __half* __restrict__ h, int n4)
{
    int i = blockIdx.x * blockDim.x + threadIdx.x;
    if (i < n4) {
        float4 v = ((const float4*)src)[i];
        __half2* o = (__half2*)(h + i * 4);
        o[0] = __floats2half2_rn(v.x, v.y);
        o[1] = __floats2half2_rn(v.z, v.w);
    }
}

// ---------------------------------------------------------------------------
// GEMM: out[b][m][n] = sum_c W[m][c] * X[b][c][n] (+bias), fp16 2-term:
//   W_h * X_h + W_h * X_l   (fp32 accum)
// Block 128x128, k-chunk 32, 8 warps (2x4), cp.async double buffer.
// SPLIT_OUT=1: write fp16 hi/lo (qkv).  SPLIT_OUT=0: fp32 + bias.
// ---------------------------------------------------------------------------
#define AS_STRIDE 40
#define BS_STRIDE 136
#define A_STG (128 * AS_STRIDE)
#define B_STG (32 * BS_STRIDE)
#define G_STG (A_STG + 2 * B_STG)
#define GEMM_SMEM_BYTES (2 * G_STG * 2)

template<int SPLIT_OUT>
__global__ __launch_bounds__(256)
void gemm_mma(const __half* __restrict__ A_g,
              const __half* __restrict__ Bh_g,
              const __half* __restrict__ Bl_g,
              const float* __restrict__ bias,
              float* __restrict__ out,
              __half* __restrict__ outh,
              __half* __restrict__ outl, int M)
{
    extern __shared__ __align__(16) __half sm[];

    const int tid = threadIdx.x;
    const int lane = tid & 31, w = tid >> 5;
    const int wm = w >> 2, wn = w & 3;
    const int n0 = blockIdx.x * 128, m0 = blockIdx.y * 128, b = blockIdx.z;
    const __half* Bh_b = Bh_g + (size_t)b * C_ * NN_;
    const __half* Bl_b = Bl_g + (size_t)b * C_ * NN_;
    const int sub = lane >> 3, subr = lane & 7;

    __half* A_s[2]; __half* Bh_s[2]; __half* Bl_s[2];
#pragma unroll
    for (int s = 0; s < 2; s++) {
        __half* base = sm + s * G_STG;
        A_s[s]  = base;
        Bh_s[s] = base + A_STG;
        Bl_s[s] = base + A_STG + B_STG;
    }

    // load coords: A 128 rows x 4 segs (16B); B 32 rows x 16 segs, x2 arrays
    const int a_r = tid >> 1, a_s0 = (tid & 1) * 2;
    const int b_k = tid >> 4, b_seg = (tid & 15) * 8;

    auto prefetch = [&](int chunk, int s) {
        int c0 = chunk * 32;
#pragma unroll
        for (int j = 0; j < 2; j++) {
            int seg = a_s0 + j;
            cp16(&A_s[s][a_r * AS_STRIDE + seg * 8],
                 A_g + (size_t)(m0 + a_r) * C_ + c0 + seg * 8);
        }
#pragma unroll
        for (int j = 0; j < 2; j++) {
            int k = b_k + j * 16;
            const size_t go = (size_t)(c0 + k) * NN_ + n0 + b_seg;
            cp16(&Bh_s[s][k * BS_STRIDE + b_seg], Bh_b + go);
            cp16(&Bl_s[s][k * BS_STRIDE + b_seg], Bl_b + go);
        }
    };

    float acc[4][4][4];
#pragma unroll
    for (int i = 0; i < 4; i++)
#pragma unroll
        for (int j = 0; j < 4; j++)
#pragma unroll
            for (int k = 0; k < 4; k++) acc[i][j][k] = 0.f;

    prefetch(0, 0);
    cp_commit();

    for (int ch = 0; ch < 16; ch++) {
        int s = ch & 1;
        if (ch < 15) { prefetch(ch + 1, s ^ 1); cp_commit(); cp_wait<1>(); }
        else         { cp_wait<0>(); }
        __syncthreads();

#pragma unroll
        for (int ks = 0; ks < 2; ks++) {
            unsigned ah[4][4];
#pragma unroll
            for (int mf = 0; mf < 4; mf++) {
                int row = wm * 64 + mf * 16 + (lane & 15);
                int col = ks * 16 + (lane >> 4) * 8;
                ldm_x4(ah[mf], cvta_s(&A_s[s][row * AS_STRIDE + col]));
            }
            unsigned bhf[4][2], blf[4][2];
#pragma unroll
            for (int np = 0; np < 2; np++) {
                int nf = np * 2;
                int krow = ks * 16 + (sub & 1) * 8 + subr;
                int ncol = wn * 32 + (nf + (sub >> 1)) * 8;
                unsigned t[4];
                ldm_x4t(t, cvta_s(&Bh_s[s][krow * BS_STRIDE + ncol]));
                bhf[nf][0] = t[0]; bhf[nf][1] = t[1];
                bhf[nf + 1][0] = t[2]; bhf[nf + 1][1] = t[3];
                ldm_x4t(t, cvta_s(&Bl_s[s][krow * BS_STRIDE + ncol]));
                blf[nf][0] = t[0]; blf[nf][1] = t[1];
                blf[nf + 1][0] = t[2]; blf[nf + 1][1] = t[3];
            }
#pragma unroll
            for (int mf = 0; mf < 4; mf++)
#pragma unroll
                for (int nf = 0; nf < 4; nf++) {
                    mma16816(acc[mf][nf], ah[mf], bhf[nf][0], bhf[nf][1]);
                    mma16816(acc[mf][nf], ah[mf], blf[nf][0], blf[nf][1]);
                }
        }
        __syncthreads();
    }

    const int g = lane >> 2, tg = lane & 3;
#pragma unroll
    for (int mf = 0; mf < 4; mf++) {
        int r0 = m0 + wm * 64 + mf * 16 + g;
        int r1 = r0 + 8;
        if (SPLIT_OUT) {
            __half* oh = outh + (size_t)b * M * NN_;
            __half* ol = outl + (size_t)b * M * NN_;
#pragma unroll
            for (int nf = 0; nf < 4; nf++) {
                int cc = n0 + wn * 32 + nf * 8 + tg * 2;
                split_store_h(acc[mf][nf][0], acc[mf][nf][1],
                              &oh[(size_t)r0 * NN_ + cc], &ol[(size_t)r0 * NN_ + cc]);
                split_store_h(acc[mf][nf][2], acc[mf][nf][3],
                              &oh[(size_t)r1 * NN_ + cc], &ol[(size_t)r1 * NN_ + cc]);
            }
        } else {
            float* ob = out + (size_t)b * M * NN_;
            float bv0 = bias[r0], bv1 = bias[r1];
#pragma unroll
            for (int nf = 0; nf < 4; nf++) {
                int cc = n0 + wn * 32 + nf * 8 + tg * 2;
                *(float2*)&ob[(size_t)r0 * NN_ + cc] =
                    make_float2(acc[mf][nf][0] + bv0, acc[mf][nf][1] + bv0);
                *(float2*)&ob[(size_t)r1 * NN_ + cc] =
                    make_float2(acc[mf][nf][2] + bv1, acc[mf][nf][3] + bv1);
            }
        }
    }
}

// ---------------------------------------------------------------------------
// Fused attention, FA2 register-resident, fp16 2-term:
//   S  = Q_h^T K_h + Q_h^T K_l      (Q single; error = Q rounding)
//   PV = P_h V_h + P_h V_l          (P single; error = P rounding)
// Block = (m-tile 128, bh).  8 warps, warp owns 16 query rows.
// ---------------------------------------------------------------------------
#define QS_STRIDE 136
#define KS_STRIDE 72
#define Q_ELEMS  (64 * QS_STRIDE)
#define KV_ARR   (64 * KS_STRIDE)
#define KV_STG   (4 * KV_ARR)
#define ATTN_SMEM_BYTES ((Q_ELEMS + 2 * KV_STG) * 2)

__global__ __launch_bounds__(256)
void attn_mma(const __half* __restrict__ qkvh,
              const __half* __restrict__ qkvl,
              __half* __restrict__ aoh,
              __half* __restrict__ aol)
{
    extern __shared__ __align__(16) __half sm[];
    __half* Qh  = sm;
    __half* KVs = Qh + Q_ELEMS;          // [2 stages][Kh|Kl|Vh|Vl]
    float* Ot = (float*)sm;              // epilogue reuse [64][132]

    const int tid = threadIdx.x, lane = tid & 31, w = tid >> 5;
    const int m0 = blockIdx.x * 128, bh = blockIdx.y;
    const size_t base = (size_t)bh * 192 * NN_;
    const __half* qh = qkvh + base;
    const __half* kh = qh + (size_t)64 * NN_;
    const __half* kl = qkvl + base + (size_t)64 * NN_;
    const __half* vh = qh + (size_t)128 * NN_;
    const __half* vl = qkvl + base + (size_t)128 * NN_;
    const int sub = lane >> 3, subr = lane & 7;

    // Q load (single array): [d=64][m=128], 16 segs of 16B per row
    {
        const int d = tid >> 4, seg = (tid & 15) * 8;
#pragma unroll
        for (int j = 0; j < 4; j++) {
            int dd = d + j * 16;
            cp16(&Qh[dd * QS_STRIDE + seg], qh + (size_t)dd * NN_ + m0 + seg);
        }
    }
    // KV prefetch: 4 arrays x [64][64]; 64 rows x 4 segs = 256 tasks/array
    const int kv_d = tid >> 2, kv_seg = (tid & 3) * 16;
    auto kv_prefetch = [&](int chunk, int s) {
        __half* st = KVs + s * KV_STG;
        int n0 = chunk * 64;
        const size_t go = (size_t)kv_d * NN_ + n0 + kv_seg;
        const int so = kv_d * KS_STRIDE + kv_seg;
        cp16(&st[so],              kh + go);
        cp16(&st[KV_ARR + so],     kl + go);
        cp16(&st[2 * KV_ARR + so], vh + go);
        cp16(&st[3 * KV_ARR + so], vl + go);
        cp16(&st[so + 8],              kh + go + 8);
        cp16(&st[KV_ARR + so + 8],     kl + go + 8);
        cp16(&st[2 * KV_ARR + so + 8], vh + go + 8);
        cp16(&st[3 * KV_ARR + so + 8], vl + go + 8);
    };

    kv_prefetch(0, 0);
    cp_commit();

    float oacc[8][4] = {};
    float rmax0 = -1e30f, rmax1 = -1e30f, rsum0 = 0.f, rsum1 = 0.f;

    for (int ch = 0; ch < 16; ch++) {
        int s = ch & 1;
        if (ch < 15) { kv_prefetch(ch + 1, s ^ 1); cp_commit(); cp_wait<1>(); }
        else         { cp_wait<0>(); }
        __syncthreads();

        __half* Kh_s = KVs + s * KV_STG;
        __half* Kl_s = Kh_s + KV_ARR;
        __half* Vh_s = Kh_s + 2 * KV_ARR;
        __half* Vl_s = Kh_s + 3 * KV_ARR;

        // ---- S = Q^T K (2-term) ----
        float sacc[8][4];
#pragma unroll
        for (int i = 0; i < 8; i++) {
            sacc[i][0] = 0.f; sacc[i][1] = 0.f; sacc[i][2] = 0.f; sacc[i][3] = 0.f;
        }
#pragma unroll
        for (int ks = 0; ks < 4; ks++) {
            unsigned qa[4];
            {
                int drow = ks * 16 + (lane >> 4) * 8 + subr;
                int mcol = w * 16 + ((lane >> 3) & 1) * 8;
                ldm_x4t(qa, cvta_s(&Qh[drow * QS_STRIDE + mcol]));
            }
#pragma unroll
            for (int np = 0; np < 4; np++) {
                int nf = np * 2;
                int krow = ks * 16 + (sub & 1) * 8 + subr;
                int ncol = (nf + (sub >> 1)) * 8;
                unsigned th[4], tl[4];
                ldm_x4t(th, cvta_s(&Kh_s[krow * KS_STRIDE + ncol]));
                ldm_x4t(tl, cvta_s(&Kl_s[krow * KS_STRIDE + ncol]));
                mma16816(sacc[nf],     qa, th[0], th[1]);
                mma16816(sacc[nf],     qa, tl[0], tl[1]);
                mma16816(sacc[nf + 1], qa, th[2], th[3]);
                mma16816(sacc[nf + 1], qa, tl[2], tl[3]);
            }
        }
#pragma unroll
        for (int nf = 0; nf < 8; nf++) {
            sacc[nf][0] *= SCALE_; sacc[nf][1] *= SCALE_;
            sacc[nf][2] *= SCALE_; sacc[nf][3] *= SCALE_;
        }

        // ---- online softmax (rows quad-local) ----
        float cm0 = -1e30f, cm1 = -1e30f;
#pragma unroll
        for (int nf = 0; nf < 8; nf++) {
            cm0 = fmaxf(cm0, fmaxf(sacc[nf][0], sacc[nf][1]));
            cm1 = fmaxf(cm1, fmaxf(sacc[nf][2], sacc[nf][3]));
        }
        cm0 = fmaxf(cm0, __shfl_xor_sync(0xffffffffu, cm0, 1));
        cm0 = fmaxf(cm0, __shfl_xor_sync(0xffffffffu, cm0, 2));
        cm1 = fmaxf(cm1, __shfl_xor_sync(0xffffffffu, cm1, 1));
        cm1 = fmaxf(cm1, __shfl_xor_sync(0xffffffffu, cm1, 2));
        float nm0 = fmaxf(rmax0, cm0), nm1 = fmaxf(rmax1, cm1);
        float a0 = __expf(rmax0 - nm0), a1 = __expf(rmax1 - nm1);
        rmax0 = nm0; rmax1 = nm1;

        float ps0 = 0.f, ps1 = 0.f;
#pragma unroll
        for (int nf = 0; nf < 8; nf++) {
            sacc[nf][0] = __expf(sacc[nf][0] - nm0);
            sacc[nf][1] = __expf(sacc[nf][1] - nm0);
            sacc[nf][2] = __expf(sacc[nf][2] - nm1);
            sacc[nf][3] = __expf(sacc[nf][3] - nm1);
            ps0 += sacc[nf][0] + sacc[nf][1];
            ps1 += sacc[nf][2] + sacc[nf][3];
        }
        ps0 += __shfl_xor_sync(0xffffffffu, ps0, 1);
        ps0 += __shfl_xor_sync(0xffffffffu, ps0, 2);
        ps1 += __shfl_xor_sync(0xffffffffu, ps1, 1);
        ps1 += __shfl_xor_sync(0xffffffffu, ps1, 2);
        rsum0 = rsum0 * a0 + ps0;
        rsum1 = rsum1 * a1 + ps1;

#pragma unroll
        for (int df = 0; df < 8; df++) {
            oacc[df][0] *= a0; oacc[df][1] *= a0;
            oacc[df][2] *= a1; oacc[df][3] *= a1;
        }

        // ---- PV (2-term, P single fp16) ----
#pragma unroll
        for (int ks = 0; ks < 4; ks++) {
            unsigned ph[4];
            ph[0] = pack_h(sacc[2 * ks][0],     sacc[2 * ks][1]);
            ph[1] = pack_h(sacc[2 * ks][2],     sacc[2 * ks][3]);
            ph[2] = pack_h(sacc[2 * ks + 1][0], sacc[2 * ks + 1][1]);
            ph[3] = pack_h(sacc[2 * ks + 1][2], sacc[2 * ks + 1][3]);
#pragma unroll
            for (int dp = 0; dp < 4; dp++) {
                int df = dp * 2;
                int drow = (df + (sub >> 1)) * 8 + subr;
                int col = ks * 16 + (sub & 1) * 8;
                unsigned th[4], tl[4];
                ldm_x4(th, cvta_s(&Vh_s[drow * KS_STRIDE + col]));
                ldm_x4(tl, cvta_s(&Vl_s[drow * KS_STRIDE + col]));
                mma16816(oacc[df],     ph, th[0], th[1]);
                mma16816(oacc[df],     ph, tl[0], tl[1]);
                mma16816(oacc[df + 1], ph, th[2], th[3]);
                mma16816(oacc[df + 1], ph, tl[2], tl[3]);
            }
        }
        __syncthreads();
    }

    // ---- epilogue: normalize, transpose via smem, split-store [b][c][n] ----
    const int g = lane >> 2, tg = lane & 3;
    float i0 = 1.f / rsum0, i1 = 1.f / rsum1;
#pragma unroll
    for (int df = 0; df < 8; df++) {
        int d = df * 8 + tg * 2;
        int mr = w * 16 + g;
        Ot[(d    ) * 132 + mr    ] = oacc[df][0] * i0;
        Ot[(d + 1) * 132 + mr    ] = oacc[df][1] * i0;
        Ot[(d    ) * 132 + mr + 8] = oacc[df][2] * i1;
        Ot[(d + 1) * 132 + mr + 8] = oacc[df][3] * i1;
    }
    __syncthreads();
#pragma unroll
    for (int j = 0; j < 8; j++) {
        int idx = tid + j * 256;
        int d = idx >> 5, mb = (idx & 31) << 2;
        float4 v = *(const float4*)&Ot[d * 132 + mb];
        size_t go = (size_t)(bh * 64 + d) * NN_ + m0 + mb;
        split_store_h(v.x, v.y, aoh + go,     aol + go);
        split_store_h(v.z, v.w, aoh + go + 2, aol + go + 2);
    }
}

// ---------------------------------------------------------------------------
extern "C" void kernel_launch(void* const* d_in, const int* in_sizes, int n_in,
                              void* d_out, int out_size)
{
    const float* x      = (const float*)d_in[0];
    const float* w_qkv  = (const float*)d_in[1];
    const float* w_proj = (const float*)d_in[2];
    const float* b_proj = (const float*)d_in[3];
    float* out = (float*)d_out;

    __half *xh, *xl, *wq, *wp, *qkvh, *qkvl, *aoh, *aol;
    cudaGetSymbolAddress((void**)&xh,  g_xh);  cudaGetSymbolAddress((void**)&xl,  g_xl);
    cudaGetSymbolAddress((void**)&wq,  g_wq);  cudaGetSymbolAddress((void**)&wp,  g_wp);
    cudaGetSymbolAddress((void**)&qkvh, g_qkvh); cudaGetSymbolAddress((void**)&qkvl, g_qkvl);
    cudaGetSymbolAddress((void**)&aoh, g_aoh); cudaGetSymbolAddress((void**)&aol, g_aol);

    cudaFuncSetAttribute(gemm_mma<1>,
        cudaFuncAttributeMaxDynamicSharedMemorySize, GEMM_SMEM_BYTES);
    cudaFuncSetAttribute(gemm_mma<0>,
        cudaFuncAttributeMaxDynamicSharedMemorySize, GEMM_SMEM_BYTES);
    cudaFuncSetAttribute(attn_mma,
        cudaFuncAttributeMaxDynamicSharedMemorySize, ATTN_SMEM_BYTES);

    // 0) convert inputs
    split_f32h<<<(B_ * C_ * NN_ / 4 + 255) / 256, 256>>>(x, xh, xl, B_ * C_ * NN_ / 4);
    conv_f32h<<<(MQKV_ * C_ / 4 + 255) / 256, 256>>>(w_qkv, wq, MQKV_ * C_ / 4);
    conv_f32h<<<(C_ * C_ / 4 + 255) / 256, 256>>>(w_proj, wp, C_ * C_ / 4);

    // 1) QKV GEMM -> split qkv [b][o][n]
    gemm_mma<1><<<dim3(8, 12, 8), 256, GEMM_SMEM_BYTES>>>(
        wq, xh, xl, nullptr, nullptr, qkvh, qkvl, MQKV_);
    // 2) attention -> split ao [b][c][n]
    attn_mma<<<dim3(8, 64), 256, ATTN_SMEM_BYTES>>>(qkvh, qkvl, aoh, aol);
    // 3) proj GEMM -> fp32 out (+bias)
    gemm_mma<0><<<dim3(8, 4, 8), 256, GEMM_SMEM_BYTES>>>(
        wp, aoh, aol, b_proj, out, nullptr, nullptr, C_);
}

// round 7
// speedup vs baseline: 7.2195x; 1.0066x over previous
#include <cuda_runtime.h>
#include <cuda_fp16.h>

#define B_     8
#define C_     512
#define NN_    1024
#define MQKV_  1536
#define SCALE_ 0.125f

// ---------------------------------------------------------------------------
// Scratch: fp16 operands.  A-side (weights / Q / P) single fp16; B-side split.
// ---------------------------------------------------------------------------
__device__ __half g_xh [B_ * C_ * NN_];
__device__ __half g_xl [B_ * C_ * NN_];
__device__ __half g_wq [MQKV_ * C_];
__device__ __half g_wp [C_ * C_];
__device__ __half g_qkvh[B_ * MQKV_ * NN_];
__device__ __half g_qkvl[B_ * MQKV_ * NN_];
__device__ __half g_aoh[B_ * C_ * NN_];
__device__ __half g_aol[B_ * C_ * NN_];

// ---------------------------------------------------------------------------
// helpers
// ---------------------------------------------------------------------------
__device__ __forceinline__ unsigned cvta_s(const void* p) {
    return (unsigned)__cvta_generic_to_shared(p);
}
__device__ __forceinline__ void ldm_x4(unsigned* r, unsigned a) {
    asm volatile("ldmatrix.sync.aligned.m8n8.x4.shared.b16 {%0,%1,%2,%3},[%4];"
        : "=r"(r[0]), "=r"(r[1]), "=r"(r[2]), "=r"(r[3]) : "r"(a));
}
__device__ __forceinline__ void ldm_x4t(unsigned* r, unsigned a) {
    asm volatile("ldmatrix.sync.aligned.m8n8.x4.trans.shared.b16 {%0,%1,%2,%3},[%4];"
        : "=r"(r[0]), "=r"(r[1]), "=r"(r[2]), "=r"(r[3]) : "r"(a));
}
__device__ __forceinline__ void mma16816(float* c, const unsigned* a,
                                         unsigned b0, unsigned b1) {
    asm volatile("mma.sync.aligned.m16n8k16.row.col.f32.f16.f16.f32 "
        "{%0,%1,%2,%3},{%4,%5,%6,%7},{%8,%9},{%0,%1,%2,%3};"
        : "+f"(c[0]), "+f"(c[1]), "+f"(c[2]), "+f"(c[3])
        : "r"(a[0]), "r"(a[1]), "r"(a[2]), "r"(a[3]), "r"(b0), "r"(b1));
}
__device__ __forceinline__ void cp16(void* s, const void* g) {
    asm volatile("cp.async.cg.shared.global [%0],[%1],16;"
        :: "r"(cvta_s(s)), "l"(g));
}
__device__ __forceinline__ void cp_commit() {
    asm volatile("cp.async.commit_group;");
}
template<int N> __device__ __forceinline__ void cp_wait() {
    asm volatile("cp.async.wait_group %0;" :: "n"(N));
}
__device__ __forceinline__ unsigned pack_h(float a, float b) {
    __half2 h = __floats2half2_rn(a, b);
    return *reinterpret_cast<unsigned*>(&h);
}
__device__ __forceinline__ void split_store_h(float a, float b,
                                              __half* ph, __half* pl) {
    __half ah = __float2half_rn(a), bh = __float2half_rn(b);
    *reinterpret_cast<__half2*>(ph) = __halves2half2(ah, bh);
    *reinterpret_cast<__half2*>(pl) =
        __floats2half2_rn(a - __half2float(ah), b - __half2float(bh));
}

// ---------------------------------------------------------------------------
// Conversion kernels
// ---------------------------------------------------------------------------
__global__ void split_f32h(const float* __restrict__ src,
                           __half* __restrict__ h, __half* __restrict__ l, int n4)
{
    int i = blockIdx.x * blockDim.x + threadIdx.x;
    if (i < n4) {
        float4 v = ((const float4*)src)[i];
        split_store_h(v.x, v.y, h + i * 4,     l + i * 4);
        split_store_h(v.z, v.w, h + i * 4 + 2, l + i * 4 + 2);
    }
}
__global__ void conv_f32h(const float* __restrict__ src,
                          __half* __restrict__ h, int n4)
{
    int i = blockIdx.x * blockDim.x + threadIdx.x;
    if (i < n4) {
        float4 v = ((const float4*)src)[i];
        __half2* o = (__half2*)(h + i * 4);
        o[0] = __floats2half2_rn(v.x, v.y);
        o[1] = __floats2half2_rn(v.z, v.w);
    }
}

// ---------------------------------------------------------------------------
// GEMM: out[b][m][n] = sum_c W[m][c] * X[b][c][n] (+bias), fp16 2-term:
//   W_h * X_h + W_h * X_l   (fp32 accum)
// Block 128x128, k-chunk 32, 8 warps (2x4), cp.async 3-stage ring,
// ONE __syncthreads per chunk.
// ---------------------------------------------------------------------------
#define AS_STRIDE 40
#define BS_STRIDE 136
#define A_STG (128 * AS_STRIDE)
#define B_STG (32 * BS_STRIDE)
#define G_STG (A_STG + 2 * B_STG)
#define GEMM_SMEM_BYTES (3 * G_STG * 2)

template<int SPLIT_OUT>
__global__ __launch_bounds__(256, 2)
void gemm_mma(const __half* __restrict__ A_g,
              const __half* __restrict__ Bh_g,
              const __half* __restrict__ Bl_g,
              const float* __restrict__ bias,
              float* __restrict__ out,
              __half* __restrict__ outh,
              __half* __restrict__ outl, int M)
{
    extern __shared__ __align__(16) __half sm[];

    const int tid = threadIdx.x;
    const int lane = tid & 31, w = tid >> 5;
    const int wm = w >> 2, wn = w & 3;
    const int n0 = blockIdx.x * 128, m0 = blockIdx.y * 128, b = blockIdx.z;
    const __half* Bh_b = Bh_g + (size_t)b * C_ * NN_;
    const __half* Bl_b = Bl_g + (size_t)b * C_ * NN_;
    const int sub = lane >> 3, subr = lane & 7;

    // load coords: A 128 rows x 4 segs (16B); B 32 rows x 16 segs, x2 arrays
    const int a_r = tid >> 1, a_s0 = (tid & 1) * 2;
    const int b_k = tid >> 4, b_seg = (tid & 15) * 8;

    auto prefetch = [&](int chunk, int s) {
        __half* base = sm + s * G_STG;
        __half* A_s  = base;
        __half* Bh_s = base + A_STG;
        __half* Bl_s = base + A_STG + B_STG;
        int c0 = chunk * 32;
#pragma unroll
        for (int j = 0; j < 2; j++) {
            int seg = a_s0 + j;
            cp16(&A_s[a_r * AS_STRIDE + seg * 8],
                 A_g + (size_t)(m0 + a_r) * C_ + c0 + seg * 8);
        }
#pragma unroll
        for (int j = 0; j < 2; j++) {
            int k = b_k + j * 16;
            const size_t go = (size_t)(c0 + k) * NN_ + n0 + b_seg;
            cp16(&Bh_s[k * BS_STRIDE + b_seg], Bh_b + go);
            cp16(&Bl_s[k * BS_STRIDE + b_seg], Bl_b + go);
        }
    };

    float acc[4][4][4];
#pragma unroll
    for (int i = 0; i < 4; i++)
#pragma unroll
        for (int j = 0; j < 4; j++)
#pragma unroll
            for (int k = 0; k < 4; k++) acc[i][j][k] = 0.f;

    prefetch(0, 0); cp_commit();
    prefetch(1, 1); cp_commit();

    int s = 0;
    for (int ch = 0; ch < 16; ch++) {
        if (ch + 1 < 16) cp_wait<1>(); else cp_wait<0>();
        __syncthreads();
        if (ch + 2 < 16) {
            int sn = s + 2; if (sn >= 3) sn -= 3;
            prefetch(ch + 2, sn);
            cp_commit();
        }

        __half* base = sm + s * G_STG;
        __half* A_s  = base;
        __half* Bh_s = base + A_STG;
        __half* Bl_s = base + A_STG + B_STG;

#pragma unroll
        for (int ks = 0; ks < 2; ks++) {
            unsigned ah[4][4];
#pragma unroll
            for (int mf = 0; mf < 4; mf++) {
                int row = wm * 64 + mf * 16 + (lane & 15);
                int col = ks * 16 + (lane >> 4) * 8;
                ldm_x4(ah[mf], cvta_s(&A_s[row * AS_STRIDE + col]));
            }
            unsigned bhf[4][2], blf[4][2];
#pragma unroll
            for (int np = 0; np < 2; np++) {
                int nf = np * 2;
                int krow = ks * 16 + (sub & 1) * 8 + subr;
                int ncol = wn * 32 + (nf + (sub >> 1)) * 8;
                unsigned t[4];
                ldm_x4t(t, cvta_s(&Bh_s[krow * BS_STRIDE + ncol]));
                bhf[nf][0] = t[0]; bhf[nf][1] = t[1];
                bhf[nf + 1][0] = t[2]; bhf[nf + 1][1] = t[3];
                ldm_x4t(t, cvta_s(&Bl_s[krow * BS_STRIDE + ncol]));
                blf[nf][0] = t[0]; blf[nf][1] = t[1];
                blf[nf + 1][0] = t[2]; blf[nf + 1][1] = t[3];
            }
#pragma unroll
            for (int mf = 0; mf < 4; mf++)
#pragma unroll
                for (int nf = 0; nf < 4; nf++) {
                    mma16816(acc[mf][nf], ah[mf], bhf[nf][0], bhf[nf][1]);
                    mma16816(acc[mf][nf], ah[mf], blf[nf][0], blf[nf][1]);
                }
        }
        if (++s >= 3) s -= 3;
    }

    const int g = lane >> 2, tg = lane & 3;
#pragma unroll
    for (int mf = 0; mf < 4; mf++) {
        int r0 = m0 + wm * 64 + mf * 16 + g;
        int r1 = r0 + 8;
        if (SPLIT_OUT) {
            __half* oh = outh + (size_t)b * M * NN_;
            __half* ol = outl + (size_t)b * M * NN_;
#pragma unroll
            for (int nf = 0; nf < 4; nf++) {
                int cc = n0 + wn * 32 + nf * 8 + tg * 2;
                split_store_h(acc[mf][nf][0], acc[mf][nf][1],
                              &oh[(size_t)r0 * NN_ + cc], &ol[(size_t)r0 * NN_ + cc]);
                split_store_h(acc[mf][nf][2], acc[mf][nf][3],
                              &oh[(size_t)r1 * NN_ + cc], &ol[(size_t)r1 * NN_ + cc]);
            }
        } else {
            float* ob = out + (size_t)b * M * NN_;
            float bv0 = bias[r0], bv1 = bias[r1];
#pragma unroll
            for (int nf = 0; nf < 4; nf++) {
                int cc = n0 + wn * 32 + nf * 8 + tg * 2;
                *(float2*)&ob[(size_t)r0 * NN_ + cc] =
                    make_float2(acc[mf][nf][0] + bv0, acc[mf][nf][1] + bv0);
                *(float2*)&ob[(size_t)r1 * NN_ + cc] =
                    make_float2(acc[mf][nf][2] + bv1, acc[mf][nf][3] + bv1);
            }
        }
    }
}

// ---------------------------------------------------------------------------
// Fused attention, FA2 register-resident, fp16 2-term.  2 CTAs/SM.
// ---------------------------------------------------------------------------
#define QS_STRIDE 136
#define KS_STRIDE 72
#define Q_ELEMS  (64 * QS_STRIDE)
#define KV_ARR   (64 * KS_STRIDE)
#define KV_STG   (4 * KV_ARR)
#define ATTN_SMEM_BYTES ((Q_ELEMS + 2 * KV_STG) * 2)

__global__ __launch_bounds__(256, 2)
void attn_mma(const __half* __restrict__ qkvh,
              const __half* __restrict__ qkvl,
              __half* __restrict__ aoh,
              __half* __restrict__ aol)
{
    extern __shared__ __align__(16) __half sm[];
    __half* Qh  = sm;
    __half* KVs = Qh + Q_ELEMS;          // [2 stages][Kh|Kl|Vh|Vl]
    float* Ot = (float*)sm;              // epilogue reuse [64][132]

    const int tid = threadIdx.x, lane = tid & 31, w = tid >> 5;
    const int m0 = blockIdx.x * 128, bh = blockIdx.y;
    const size_t base = (size_t)bh * 192 * NN_;
    const __half* qh = qkvh + base;
    const __half* kh = qh + (size_t)64 * NN_;
    const __half* kl = qkvl + base + (size_t)64 * NN_;
    const __half* vh = qh + (size_t)128 * NN_;
    const __half* vl = qkvl + base + (size_t)128 * NN_;
    const int sub = lane >> 3, subr = lane & 7;

    // Q load (single array): [d=64][m=128], 16 segs of 16B per row
    {
        const int d = tid >> 4, seg = (tid & 15) * 8;
#pragma unroll
        for (int j = 0; j < 4; j++) {
            int dd = d + j * 16;
            cp16(&Qh[dd * QS_STRIDE + seg], qh + (size_t)dd * NN_ + m0 + seg);
        }
    }
    // KV prefetch: 4 arrays x [64][64]
    const int kv_d = tid >> 2, kv_seg = (tid & 3) * 16;
    auto kv_prefetch = [&](int chunk, int s) {
        __half* st = KVs + s * KV_STG;
        int n0 = chunk * 64;
        const size_t go = (size_t)kv_d * NN_ + n0 + kv_seg;
        const int so = kv_d * KS_STRIDE + kv_seg;
        cp16(&st[so],              kh + go);
        cp16(&st[KV_ARR + so],     kl + go);
        cp16(&st[2 * KV_ARR + so], vh + go);
        cp16(&st[3 * KV_ARR + so], vl + go);
        cp16(&st[so + 8],              kh + go + 8);
        cp16(&st[KV_ARR + so + 8],     kl + go + 8);
        cp16(&st[2 * KV_ARR + so + 8], vh + go + 8);
        cp16(&st[3 * KV_ARR + so + 8], vl + go + 8);
    };

    kv_prefetch(0, 0);
    cp_commit();

    float oacc[8][4] = {};
    float rmax0 = -1e30f, rmax1 = -1e30f, rsum0 = 0.f, rsum1 = 0.f;

    for (int ch = 0; ch < 16; ch++) {
        int s = ch & 1;
        if (ch < 15) { kv_prefetch(ch + 1, s ^ 1); cp_commit(); cp_wait<1>(); }
        else         { cp_wait<0>(); }
        __syncthreads();

        __half* Kh_s = KVs + s * KV_STG;
        __half* Kl_s = Kh_s + KV_ARR;
        __half* Vh_s = Kh_s + 2 * KV_ARR;
        __half* Vl_s = Kh_s + 3 * KV_ARR;

        // ---- S = Q^T K (2-term) ----
        float sacc[8][4];
#pragma unroll
        for (int i = 0; i < 8; i++) {
            sacc[i][0] = 0.f; sacc[i][1] = 0.f; sacc[i][2] = 0.f; sacc[i][3] = 0.f;
        }
#pragma unroll
        for (int ks = 0; ks < 4; ks++) {
            unsigned qa[4];
            {
                int drow = ks * 16 + (lane >> 4) * 8 + subr;
                int mcol = w * 16 + ((lane >> 3) & 1) * 8;
                ldm_x4t(qa, cvta_s(&Qh[drow * QS_STRIDE + mcol]));
            }
#pragma unroll
            for (int np = 0; np < 4; np++) {
                int nf = np * 2;
                int krow = ks * 16 + (sub & 1) * 8 + subr;
                int ncol = (nf + (sub >> 1)) * 8;
                unsigned th[4], tl[4];
                ldm_x4t(th, cvta_s(&Kh_s[krow * KS_STRIDE + ncol]));
                ldm_x4t(tl, cvta_s(&Kl_s[krow * KS_STRIDE + ncol]));
                mma16816(sacc[nf],     qa, th[0], th[1]);
                mma16816(sacc[nf],     qa, tl[0], tl[1]);
                mma16816(sacc[nf + 1], qa, th[2], th[3]);
                mma16816(sacc[nf + 1], qa, tl[2], tl[3]);
            }
        }
#pragma unroll
        for (int nf = 0; nf < 8; nf++) {
            sacc[nf][0] *= SCALE_; sacc[nf][1] *= SCALE_;
            sacc[nf][2] *= SCALE_; sacc[nf][3] *= SCALE_;
        }

        // ---- online softmax (rows quad-local) ----
        float cm0 = -1e30f, cm1 = -1e30f;
#pragma unroll
        for (int nf = 0; nf < 8; nf++) {
            cm0 = fmaxf(cm0, fmaxf(sacc[nf][0], sacc[nf][1]));
            cm1 = fmaxf(cm1, fmaxf(sacc[nf][2], sacc[nf][3]));
        }
        cm0 = fmaxf(cm0, __shfl_xor_sync(0xffffffffu, cm0, 1));
        cm0 = fmaxf(cm0, __shfl_xor_sync(0xffffffffu, cm0, 2));
        cm1 = fmaxf(cm1, __shfl_xor_sync(0xffffffffu, cm1, 1));
        cm1 = fmaxf(cm1, __shfl_xor_sync(0xffffffffu, cm1, 2));
        float nm0 = fmaxf(rmax0, cm0), nm1 = fmaxf(rmax1, cm1);
        float a0 = __expf(rmax0 - nm0), a1 = __expf(rmax1 - nm1);
        rmax0 = nm0; rmax1 = nm1;

        float ps0 = 0.f, ps1 = 0.f;
#pragma unroll
        for (int nf = 0; nf < 8; nf++) {
            sacc[nf][0] = __expf(sacc[nf][0] - nm0);
            sacc[nf][1] = __expf(sacc[nf][1] - nm0);
            sacc[nf][2] = __expf(sacc[nf][2] - nm1);
            sacc[nf][3] = __expf(sacc[nf][3] - nm1);
            ps0 += sacc[nf][0] + sacc[nf][1];
            ps1 += sacc[nf][2] + sacc[nf][3];
        }
        ps0 += __shfl_xor_sync(0xffffffffu, ps0, 1);
        ps0 += __shfl_xor_sync(0xffffffffu, ps0, 2);
        ps1 += __shfl_xor_sync(0xffffffffu, ps1, 1);
        ps1 += __shfl_xor_sync(0xffffffffu, ps1, 2);
        rsum0 = rsum0 * a0 + ps0;
        rsum1 = rsum1 * a1 + ps1;

#pragma unroll
        for (int df = 0; df < 8; df++) {
            oacc[df][0] *= a0; oacc[df][1] *= a0;
            oacc[df][2] *= a1; oacc[df][3] *= a1;
        }

        // ---- PV (2-term, P single fp16) ----
#pragma unroll
        for (int ks = 0; ks < 4; ks++) {
            unsigned ph[4];
            ph[0] = pack_h(sacc[2 * ks][0],     sacc[2 * ks][1]);
            ph[1] = pack_h(sacc[2 * ks][2],     sacc[2 * ks][3]);
            ph[2] = pack_h(sacc[2 * ks + 1][0], sacc[2 * ks + 1][1]);
            ph[3] = pack_h(sacc[2 * ks + 1][2], sacc[2 * ks + 1][3]);
#pragma unroll
            for (int dp = 0; dp < 4; dp++) {
                int df = dp * 2;
                int drow = (df + (sub >> 1)) * 8 + subr;
                int col = ks * 16 + (sub & 1) * 8;
                unsigned th[4], tl[4];
                ldm_x4(th, cvta_s(&Vh_s[drow * KS_STRIDE + col]));
                ldm_x4(tl, cvta_s(&Vl_s[drow * KS_STRIDE + col]));
                mma16816(oacc[df],     ph, th[0], th[1]);
                mma16816(oacc[df],     ph, tl[0], tl[1]);
                mma16816(oacc[df + 1], ph, th[2], th[3]);
                mma16816(oacc[df + 1], ph, tl[2], tl[3]);
            }
        }
        __syncthreads();
    }

    // ---- epilogue: normalize, transpose via smem, split-store [b][c][n] ----
    const int g = lane >> 2, tg = lane & 3;
    float i0 = 1.f / rsum0, i1 = 1.f / rsum1;
#pragma unroll
    for (int df = 0; df < 8; df++) {
        int d = df * 8 + tg * 2;
        int mr = w * 16 + g;
        Ot[(d    ) * 132 + mr    ] = oacc[df][0] * i0;
        Ot[(d + 1) * 132 + mr    ] = oacc[df][1] * i0;
        Ot[(d    ) * 132 + mr + 8] = oacc[df][2] * i1;
        Ot[(d + 1) * 132 + mr + 8] = oacc[df][3] * i1;
    }
    __syncthreads();
#pragma unroll
    for (int j = 0; j < 8; j++) {
        int idx = tid + j * 256;
        int d = idx >> 5, mb = (idx & 31) << 2;
        float4 v = *(const float4*)&Ot[d * 132 + mb];
        size_t go = (size_t)(bh * 64 + d) * NN_ + m0 + mb;
        split_store_h(v.x, v.y, aoh + go,     aol + go);
        split_store_h(v.z, v.w, aoh + go + 2, aol + go + 2);
    }
}

// ---------------------------------------------------------------------------
extern "C" void kernel_launch(void* const* d_in, const int* in_sizes, int n_in,
                              void* d_out, int out_size)
{
    const float* x      = (const float*)d_in[0];
    const float* w_qkv  = (const float*)d_in[1];
    const float* w_proj = (const float*)d_in[2];
    const float* b_proj = (const float*)d_in[3];
    float* out = (float*)d_out;

    __half *xh, *xl, *wq, *wp, *qkvh, *qkvl, *aoh, *aol;
    cudaGetSymbolAddress((void**)&xh,  g_xh);  cudaGetSymbolAddress((void**)&xl,  g_xl);
    cudaGetSymbolAddress((void**)&wq,  g_wq);  cudaGetSymbolAddress((void**)&wp,  g_wp);
    cudaGetSymbolAddress((void**)&qkvh, g_qkvh); cudaGetSymbolAddress((void**)&qkvl, g_qkvl);
    cudaGetSymbolAddress((void**)&aoh, g_aoh); cudaGetSymbolAddress((void**)&aol, g_aol);

    cudaFuncSetAttribute(gemm_mma<1>,
        cudaFuncAttributeMaxDynamicSharedMemorySize, GEMM_SMEM_BYTES);
    cudaFuncSetAttribute(gemm_mma<0>,
        cudaFuncAttributeMaxDynamicSharedMemorySize, GEMM_SMEM_BYTES);
    cudaFuncSetAttribute(attn_mma,
        cudaFuncAttributeMaxDynamicSharedMemorySize, ATTN_SMEM_BYTES);

    // 0) convert inputs
    split_f32h<<<(B_ * C_ * NN_ / 4 + 255) / 256, 256>>>(x, xh, xl, B_ * C_ * NN_ / 4);
    conv_f32h<<<(MQKV_ * C_ / 4 + 255) / 256, 256>>>(w_qkv, wq, MQKV_ * C_ / 4);
    conv_f32h<<<(C_ * C_ / 4 + 255) / 256, 256>>>(w_proj, wp, C_ * C_ / 4);

    // 1) QKV GEMM -> split qkv [b][o][n]
    gemm_mma<1><<<dim3(8, 12, 8), 256, GEMM_SMEM_BYTES>>>(
        wq, xh, xl, nullptr, nullptr, qkvh, qkvl, MQKV_);
    // 2) attention -> split ao [b][c][n]
    attn_mma<<<dim3(8, 64), 256, ATTN_SMEM_BYTES>>>(qkvh, qkvl, aoh, aol);
    // 3) proj GEMM -> fp32 out (+bias)
    gemm_mma<0><<<dim3(8, 4, 8), 256, GEMM_SMEM_BYTES>>>(
        wp, aoh, aol, b_proj, out, nullptr, nullptr, C_);
}

// round 8
// speedup vs baseline: 11.4236x; 1.5823x over previous
#include <cuda_runtime.h>
#include <cuda_fp16.h>

#define B_     8
#define C_     512
#define NN_    1024
#define MQKV_  1536
#define SCALE_ 0.125f

// ---------------------------------------------------------------------------
// Scratch: single fp16 operands everywhere (fp32 accum in all GEMMs)
// ---------------------------------------------------------------------------
__device__ __half g_x  [B_ * C_ * NN_];
__device__ __half g_wq [MQKV_ * C_];
__device__ __half g_wp [C_ * C_];
__device__ __half g_qkv[B_ * MQKV_ * NN_];
__device__ __half g_ao [B_ * C_ * NN_];

// ---------------------------------------------------------------------------
// helpers
// ---------------------------------------------------------------------------
__device__ __forceinline__ unsigned cvta_s(const void* p) {
    return (unsigned)__cvta_generic_to_shared(p);
}
__device__ __forceinline__ void ldm_x4(unsigned* r, unsigned a) {
    asm volatile("ldmatrix.sync.aligned.m8n8.x4.shared.b16 {%0,%1,%2,%3},[%4];"
        : "=r"(r[0]), "=r"(r[1]), "=r"(r[2]), "=r"(r[3]) : "r"(a));
}
__device__ __forceinline__ void ldm_x4t(unsigned* r, unsigned a) {
    asm volatile("ldmatrix.sync.aligned.m8n8.x4.trans.shared.b16 {%0,%1,%2,%3},[%4];"
        : "=r"(r[0]), "=r"(r[1]), "=r"(r[2]), "=r"(r[3]) : "r"(a));
}
__device__ __forceinline__ void mma16816(float* c, const unsigned* a,
                                         unsigned b0, unsigned b1) {
    asm volatile("mma.sync.aligned.m16n8k16.row.col.f32.f16.f16.f32 "
        "{%0,%1,%2,%3},{%4,%5,%6,%7},{%8,%9},{%0,%1,%2,%3};"
        : "+f"(c[0]), "+f"(c[1]), "+f"(c[2]), "+f"(c[3])
        : "r"(a[0]), "r"(a[1]), "r"(a[2]), "r"(a[3]), "r"(b0), "r"(b1));
}
__device__ __forceinline__ void cp16(void* s, const void* g) {
    asm volatile("cp.async.cg.shared.global [%0],[%1],16;"
        :: "r"(cvta_s(s)), "l"(g));
}
__device__ __forceinline__ void cp_commit() {
    asm volatile("cp.async.commit_group;");
}
template<int N> __device__ __forceinline__ void cp_wait() {
    asm volatile("cp.async.wait_group %0;" :: "n"(N));
}
__device__ __forceinline__ unsigned pack_h(float a, float b) {
    __half2 h = __floats2half2_rn(a, b);
    return *reinterpret_cast<unsigned*>(&h);
}

// ---------------------------------------------------------------------------
// fp32 -> fp16 conversion
// ---------------------------------------------------------------------------
__global__ void conv_f32h(const float* __restrict__ src,
                          __half* __restrict__ h, int n4)
{
    int i = blockIdx.x * blockDim.x + threadIdx.x;
    if (i < n4) {
        float4 v = ((const float4*)src)[i];
        __half2* o = (__half2*)(h + i * 4);
        o[0] = __floats2half2_rn(v.x, v.y);
        o[1] = __floats2half2_rn(v.z, v.w);
    }
}

// ---------------------------------------------------------------------------
// GEMM: out[b][m][n] = sum_c W[m][c] * X[b][c][n] (+bias), fp16 single-term,
// fp32 accum.  Block 128x128, k-chunk 32, 8 warps (2x4), 3-stage cp.async.
// HALF_OUT=1: write fp16 (qkv).  HALF_OUT=0: fp32 + bias (final out).
// ---------------------------------------------------------------------------
#define AS_STRIDE 40
#define BS_STRIDE 136
#define A_STG (128 * AS_STRIDE)
#define B_STG (32 * BS_STRIDE)
#define G_STG (A_STG + B_STG)
#define GEMM_SMEM_BYTES (3 * G_STG * 2)

template<int HALF_OUT>
__global__ __launch_bounds__(256, 2)
void gemm_mma(const __half* __restrict__ A_g,
              const __half* __restrict__ B_g,
              const float* __restrict__ bias,
              float* __restrict__ out,
              __half* __restrict__ outh, int M)
{
    extern __shared__ __align__(16) __half sm[];

    const int tid = threadIdx.x;
    const int lane = tid & 31, w = tid >> 5;
    const int wm = w >> 2, wn = w & 3;
    const int n0 = blockIdx.x * 128, m0 = blockIdx.y * 128, b = blockIdx.z;
    const __half* B_b = B_g + (size_t)b * C_ * NN_;
    const int sub = lane >> 3, subr = lane & 7;

    // load coords: A 128 rows x 4 segs of 16B; B 32 rows x 16 segs
    const int a_r = tid >> 1, a_s0 = (tid & 1) * 2;
    const int b_k = tid >> 4, b_seg = (tid & 15) * 8;

    auto prefetch = [&](int chunk, int s) {
        __half* A_s = sm + s * G_STG;
        __half* B_s = A_s + A_STG;
        int c0 = chunk * 32;
#pragma unroll
        for (int j = 0; j < 2; j++) {
            int seg = a_s0 + j;
            cp16(&A_s[a_r * AS_STRIDE + seg * 8],
                 A_g + (size_t)(m0 + a_r) * C_ + c0 + seg * 8);
        }
#pragma unroll
        for (int j = 0; j < 2; j++) {
            int k = b_k + j * 16;
            cp16(&B_s[k * BS_STRIDE + b_seg],
                 B_b + (size_t)(c0 + k) * NN_ + n0 + b_seg);
        }
    };

    float acc[4][4][4];
#pragma unroll
    for (int i = 0; i < 4; i++)
#pragma unroll
        for (int j = 0; j < 4; j++)
#pragma unroll
            for (int k = 0; k < 4; k++) acc[i][j][k] = 0.f;

    prefetch(0, 0); cp_commit();
    prefetch(1, 1); cp_commit();

    int s = 0;
    for (int ch = 0; ch < 16; ch++) {
        if (ch + 1 < 16) cp_wait<1>(); else cp_wait<0>();
        __syncthreads();
        if (ch + 2 < 16) {
            int sn = s + 2; if (sn >= 3) sn -= 3;
            prefetch(ch + 2, sn);
            cp_commit();
        }

        __half* A_s = sm + s * G_STG;
        __half* B_s = A_s + A_STG;

#pragma unroll
        for (int ks = 0; ks < 2; ks++) {
            unsigned ah[4][4];
#pragma unroll
            for (int mf = 0; mf < 4; mf++) {
                int row = wm * 64 + mf * 16 + (lane & 15);
                int col = ks * 16 + (lane >> 4) * 8;
                ldm_x4(ah[mf], cvta_s(&A_s[row * AS_STRIDE + col]));
            }
            unsigned bf[4][2];
#pragma unroll
            for (int np = 0; np < 2; np++) {
                int nf = np * 2;
                int krow = ks * 16 + (sub & 1) * 8 + subr;
                int ncol = wn * 32 + (nf + (sub >> 1)) * 8;
                unsigned t[4];
                ldm_x4t(t, cvta_s(&B_s[krow * BS_STRIDE + ncol]));
                bf[nf][0] = t[0]; bf[nf][1] = t[1];
                bf[nf + 1][0] = t[2]; bf[nf + 1][1] = t[3];
            }
#pragma unroll
            for (int mf = 0; mf < 4; mf++)
#pragma unroll
                for (int nf = 0; nf < 4; nf++)
                    mma16816(acc[mf][nf], ah[mf], bf[nf][0], bf[nf][1]);
        }
        if (++s >= 3) s -= 3;
    }

    const int g = lane >> 2, tg = lane & 3;
#pragma unroll
    for (int mf = 0; mf < 4; mf++) {
        int r0 = m0 + wm * 64 + mf * 16 + g;
        int r1 = r0 + 8;
        if (HALF_OUT) {
            __half* oh = outh + (size_t)b * M * NN_;
#pragma unroll
            for (int nf = 0; nf < 4; nf++) {
                int cc = n0 + wn * 32 + nf * 8 + tg * 2;
                *(__half2*)&oh[(size_t)r0 * NN_ + cc] =
                    __floats2half2_rn(acc[mf][nf][0], acc[mf][nf][1]);
                *(__half2*)&oh[(size_t)r1 * NN_ + cc] =
                    __floats2half2_rn(acc[mf][nf][2], acc[mf][nf][3]);
            }
        } else {
            float* ob = out + (size_t)b * M * NN_;
            float bv0 = bias[r0], bv1 = bias[r1];
#pragma unroll
            for (int nf = 0; nf < 4; nf++) {
                int cc = n0 + wn * 32 + nf * 8 + tg * 2;
                *(float2*)&ob[(size_t)r0 * NN_ + cc] =
                    make_float2(acc[mf][nf][0] + bv0, acc[mf][nf][1] + bv0);
                *(float2*)&ob[(size_t)r1 * NN_ + cc] =
                    make_float2(acc[mf][nf][2] + bv1, acc[mf][nf][3] + bv1);
            }
        }
    }
}

// ---------------------------------------------------------------------------
// Fused attention, FA2 register-resident, single fp16, fp32 accum.
// ---------------------------------------------------------------------------
#define QS_STRIDE 136
#define KS_STRIDE 72
#define Q_ELEMS  (64 * QS_STRIDE)
#define KV_ARR   (64 * KS_STRIDE)
#define KV_STG   (2 * KV_ARR)
#define ATTN_SMEM_BYTES ((Q_ELEMS + 2 * KV_STG) * 2)

__global__ __launch_bounds__(256, 2)
void attn_mma(const __half* __restrict__ qkv, __half* __restrict__ ao)
{
    extern __shared__ __align__(16) __half sm[];
    __half* Qh  = sm;
    __half* KVs = Qh + Q_ELEMS;          // [2 stages][K|V]
    float* Ot = (float*)sm;              // epilogue reuse [64][132]

    const int tid = threadIdx.x, lane = tid & 31, w = tid >> 5;
    const int m0 = blockIdx.x * 128, bh = blockIdx.y;
    const size_t base = (size_t)bh * 192 * NN_;
    const __half* qp = qkv + base;
    const __half* kp = qp + (size_t)64 * NN_;
    const __half* vp = qp + (size_t)128 * NN_;
    const int sub = lane >> 3, subr = lane & 7;

    // Q load: [d=64][m=128], 16 segs of 16B per row
    {
        const int d = tid >> 4, seg = (tid & 15) * 8;
#pragma unroll
        for (int j = 0; j < 4; j++) {
            int dd = d + j * 16;
            cp16(&Qh[dd * QS_STRIDE + seg], qp + (size_t)dd * NN_ + m0 + seg);
        }
    }
    // KV prefetch: 2 arrays x [64][64]; 4 cp16/thread
    const int kv_d = tid >> 2, kv_seg = (tid & 3) * 16;
    auto kv_prefetch = [&](int chunk, int s) {
        __half* st = KVs + s * KV_STG;
        int n0 = chunk * 64;
        const size_t go = (size_t)kv_d * NN_ + n0 + kv_seg;
        const int so = kv_d * KS_STRIDE + kv_seg;
        cp16(&st[so],              kp + go);
        cp16(&st[so + 8],          kp + go + 8);
        cp16(&st[KV_ARR + so],     vp + go);
        cp16(&st[KV_ARR + so + 8], vp + go + 8);
    };

    kv_prefetch(0, 0);
    cp_commit();

    float oacc[8][4] = {};
    float rmax0 = -1e30f, rmax1 = -1e30f, rsum0 = 0.f, rsum1 = 0.f;

    for (int ch = 0; ch < 16; ch++) {
        int s = ch & 1;
        if (ch < 15) { kv_prefetch(ch + 1, s ^ 1); cp_commit(); cp_wait<1>(); }
        else         { cp_wait<0>(); }
        __syncthreads();

        __half* K_s = KVs + s * KV_STG;
        __half* V_s = K_s + KV_ARR;

        // ---- S = Q^T K ----
        float sacc[8][4];
#pragma unroll
        for (int i = 0; i < 8; i++) {
            sacc[i][0] = 0.f; sacc[i][1] = 0.f; sacc[i][2] = 0.f; sacc[i][3] = 0.f;
        }
#pragma unroll
        for (int ks = 0; ks < 4; ks++) {
            unsigned qa[4];
            {
                int drow = ks * 16 + (lane >> 4) * 8 + subr;
                int mcol = w * 16 + ((lane >> 3) & 1) * 8;
                ldm_x4t(qa, cvta_s(&Qh[drow * QS_STRIDE + mcol]));
            }
#pragma unroll
            for (int np = 0; np < 4; np++) {
                int nf = np * 2;
                int krow = ks * 16 + (sub & 1) * 8 + subr;
                int ncol = (nf + (sub >> 1)) * 8;
                unsigned th[4];
                ldm_x4t(th, cvta_s(&K_s[krow * KS_STRIDE + ncol]));
                mma16816(sacc[nf],     qa, th[0], th[1]);
                mma16816(sacc[nf + 1], qa, th[2], th[3]);
            }
        }
#pragma unroll
        for (int nf = 0; nf < 8; nf++) {
            sacc[nf][0] *= SCALE_; sacc[nf][1] *= SCALE_;
            sacc[nf][2] *= SCALE_; sacc[nf][3] *= SCALE_;
        }

        // ---- online softmax (rows quad-local) ----
        float cm0 = -1e30f, cm1 = -1e30f;
#pragma unroll
        for (int nf = 0; nf < 8; nf++) {
            cm0 = fmaxf(cm0, fmaxf(sacc[nf][0], sacc[nf][1]));
            cm1 = fmaxf(cm1, fmaxf(sacc[nf][2], sacc[nf][3]));
        }
        cm0 = fmaxf(cm0, __shfl_xor_sync(0xffffffffu, cm0, 1));
        cm0 = fmaxf(cm0, __shfl_xor_sync(0xffffffffu, cm0, 2));
        cm1 = fmaxf(cm1, __shfl_xor_sync(0xffffffffu, cm1, 1));
        cm1 = fmaxf(cm1, __shfl_xor_sync(0xffffffffu, cm1, 2));
        float nm0 = fmaxf(rmax0, cm0), nm1 = fmaxf(rmax1, cm1);
        float a0 = __expf(rmax0 - nm0), a1 = __expf(rmax1 - nm1);
        rmax0 = nm0; rmax1 = nm1;

        float ps0 = 0.f, ps1 = 0.f;
#pragma unroll
        for (int nf = 0; nf < 8; nf++) {
            sacc[nf][0] = __expf(sacc[nf][0] - nm0);
            sacc[nf][1] = __expf(sacc[nf][1] - nm0);
            sacc[nf][2] = __expf(sacc[nf][2] - nm1);
            sacc[nf][3] = __expf(sacc[nf][3] - nm1);
            ps0 += sacc[nf][0] + sacc[nf][1];
            ps1 += sacc[nf][2] + sacc[nf][3];
        }
        ps0 += __shfl_xor_sync(0xffffffffu, ps0, 1);
        ps0 += __shfl_xor_sync(0xffffffffu, ps0, 2);
        ps1 += __shfl_xor_sync(0xffffffffu, ps1, 1);
        ps1 += __shfl_xor_sync(0xffffffffu, ps1, 2);
        rsum0 = rsum0 * a0 + ps0;
        rsum1 = rsum1 * a1 + ps1;

#pragma unroll
        for (int df = 0; df < 8; df++) {
            oacc[df][0] *= a0; oacc[df][1] *= a0;
            oacc[df][2] *= a1; oacc[df][3] *= a1;
        }

        // ---- PV ----
#pragma unroll
        for (int ks = 0; ks < 4; ks++) {
            unsigned ph[4];
            ph[0] = pack_h(sacc[2 * ks][0],     sacc[2 * ks][1]);
            ph[1] = pack_h(sacc[2 * ks][2],     sacc[2 * ks][3]);
            ph[2] = pack_h(sacc[2 * ks + 1][0], sacc[2 * ks + 1][1]);
            ph[3] = pack_h(sacc[2 * ks + 1][2], sacc[2 * ks + 1][3]);
#pragma unroll
            for (int dp = 0; dp < 4; dp++) {
                int df = dp * 2;
                int drow = (df + (sub >> 1)) * 8 + subr;
                int col = ks * 16 + (sub & 1) * 8;
                unsigned th[4];
                ldm_x4(th, cvta_s(&V_s[drow * KS_STRIDE + col]));
                mma16816(oacc[df],     ph, th[0], th[1]);
                mma16816(oacc[df + 1], ph, th[2], th[3]);
            }
        }
        __syncthreads();
    }

    // ---- epilogue: normalize, transpose via smem, fp16 store [b][c][n] ----
    const int g = lane >> 2, tg = lane & 3;
    float i0 = 1.f / rsum0, i1 = 1.f / rsum1;
#pragma unroll
    for (int df = 0; df < 8; df++) {
        int d = df * 8 + tg * 2;
        int mr = w * 16 + g;
        Ot[(d    ) * 132 + mr    ] = oacc[df][0] * i0;
        Ot[(d + 1) * 132 + mr    ] = oacc[df][1] * i0;
        Ot[(d    ) * 132 + mr + 8] = oacc[df][2] * i1;
        Ot[(d + 1) * 132 + mr + 8] = oacc[df][3] * i1;
    }
    __syncthreads();
#pragma unroll
    for (int j = 0; j < 8; j++) {
        int idx = tid + j * 256;
        int d = idx >> 5, mb = (idx & 31) << 2;
        float4 v = *(const float4*)&Ot[d * 132 + mb];
        size_t go = (size_t)(bh * 64 + d) * NN_ + m0 + mb;
        __half2* o = (__half2*)(ao + go);
        o[0] = __floats2half2_rn(v.x, v.y);
        o[1] = __floats2half2_rn(v.z, v.w);
    }
}

// ---------------------------------------------------------------------------
extern "C" void kernel_launch(void* const* d_in, const int* in_sizes, int n_in,
                              void* d_out, int out_size)
{
    const float* x      = (const float*)d_in[0];
    const float* w_qkv  = (const float*)d_in[1];
    const float* w_proj = (const float*)d_in[2];
    const float* b_proj = (const float*)d_in[3];
    float* out = (float*)d_out;

    __half *xh, *wq, *wp, *qkv, *ao;
    cudaGetSymbolAddress((void**)&xh,  g_x);
    cudaGetSymbolAddress((void**)&wq,  g_wq);
    cudaGetSymbolAddress((void**)&wp,  g_wp);
    cudaGetSymbolAddress((void**)&qkv, g_qkv);
    cudaGetSymbolAddress((void**)&ao,  g_ao);

    cudaFuncSetAttribute(gemm_mma<1>,
        cudaFuncAttributeMaxDynamicSharedMemorySize, GEMM_SMEM_BYTES);
    cudaFuncSetAttribute(gemm_mma<0>,
        cudaFuncAttributeMaxDynamicSharedMemorySize, GEMM_SMEM_BYTES);
    cudaFuncSetAttribute(attn_mma,
        cudaFuncAttributeMaxDynamicSharedMemorySize, ATTN_SMEM_BYTES);

    // 0) convert inputs to fp16
    conv_f32h<<<(B_ * C_ * NN_ / 4 + 255) / 256, 256>>>(x, xh, B_ * C_ * NN_ / 4);
    conv_f32h<<<(MQKV_ * C_ / 4 + 255) / 256, 256>>>(w_qkv, wq, MQKV_ * C_ / 4);
    conv_f32h<<<(C_ * C_ / 4 + 255) / 256, 256>>>(w_proj, wp, C_ * C_ / 4);

    // 1) QKV GEMM -> fp16 qkv [b][o][n]
    gemm_mma<1><<<dim3(8, 12, 8), 256, GEMM_SMEM_BYTES>>>(
        wq, xh, nullptr, nullptr, qkv, MQKV_);
    // 2) attention -> fp16 ao [b][c][n]
    attn_mma<<<dim3(8, 64), 256, ATTN_SMEM_BYTES>>>(qkv, ao);
    // 3) proj GEMM -> fp32 out (+bias)
    gemm_mma<0><<<dim3(8, 4, 8), 256, GEMM_SMEM_BYTES>>>(
        wp, ao, b_proj, out, nullptr, C_);
}